// round 4
// baseline (speedup 1.0000x reference)
#include <cuda_runtime.h>
#include <math.h>

#define NU 100000
#define NS 200000
#define DIMK 64
#define NH 2
#define HD 128          // NH * DIMK
#define EU (NU*9)
#define ESZ (NS*9)
#define BMAX 16384
#define NUW ((NU+31)/32)
#define NSW ((NS+31)/32)

// ---------------- scratch (static device globals) -------------------------------
__device__ float g_h_u[NU*HD];
__device__ float g_h_s[NS*HD];
__device__ float g_acc_u[NU*HD];
__device__ float g_acc_s[NS*HD];
__device__ float g_den_u[NU*NH];
__device__ float g_den_s[NS*NH];
__device__ float g_el_u[NU*NH];
__device__ float g_er_u[NU*NH];
__device__ float g_el_s[NS*NH];
__device__ float g_er_s[NS*NH];
__device__ unsigned g_needb_u[NUW];
__device__ unsigned g_needb_s[NSW];
__device__ unsigned g_sflagb_u[NUW];
__device__ unsigned g_sflagb_s[NSW];
__device__ int   g_slist_u[NU];
__device__ int   g_slist_s[NS];
__device__ int2  g_medge_u[EU];
__device__ int2  g_medge_s[ESZ];
__device__ int   g_cnt[4];   // [0]=nsrc_u [1]=nsrc_s [2]=nedge_u [3]=nedge_s
__device__ float g_x[BMAX*HD];

// ---------------- helpers ------------------------------------------------------
__device__ __forceinline__ void red4(float* p, float a, float b, float c, float d) {
    asm volatile("{ .reg .u64 q; cvta.to.global.u64 q, %0;"
                 "  red.global.add.v4.f32 [q], {%1, %2, %3, %4}; }"
                 :: "l"(p), "f"(a), "f"(b), "f"(c), "f"(d) : "memory");
}

#define FCMP(v,kk) ((kk)==0?(v).x:((kk)==1?(v).y:((kk)==2?(v).z:(v).w)))

// ---------------- k_zero: reset bitmasks + counters ----------------------------
__global__ void k_zero() {
    int i = blockIdx.x*blockDim.x + threadIdx.x;
    int st = gridDim.x*blockDim.x;
    for (int j = i; j < NUW; j += st) { g_needb_u[j] = 0u; g_sflagb_u[j] = 0u; }
    for (int j = i; j < NSW; j += st) { g_needb_s[j] = 0u; g_sflagb_s[j] = 0u; }
    if (i < 4) g_cnt[i] = 0;
}

// ---------------- k_mark: mark needed dsts (bits), zero their acc/den rows -----
__global__ void __launch_bounds__(128) k_mark(const int* __restrict__ uidx,
                                              const int* __restrict__ sidx) {
    int b = blockIdx.x, t = threadIdx.x;
    int u = uidx[b], s = sidx[b];
    g_acc_u[u*HD + t] = 0.f;
    g_acc_s[s*HD + t] = 0.f;
    if (t < NH) { g_den_u[u*NH + t] = 0.f; g_den_s[s*NH + t] = 0.f; }
    if (t == 0) {
        atomicOr(&g_needb_u[u >> 5], 1u << (u & 31));
        atomicOr(&g_needb_s[s >> 5], 1u << (s & 31));
    }
}

// ---------------- k_compact (merged): filter edges by needed dst; dedupe srcs --
__global__ void __launch_bounds__(256) k_compact(const int* __restrict__ usrc,
                                                 const int* __restrict__ udst, int Eu,
                                                 const int* __restrict__ ssrc,
                                                 const int* __restrict__ sdst, int Es,
                                                 int splitBlk) {
    int user = (blockIdx.x < splitBlk);
    const int* __restrict__ src = user ? usrc : ssrc;
    const int* __restrict__ dst = user ? udst : sdst;
    int E = user ? Eu : Es;
    const unsigned* __restrict__ needb = user ? g_needb_u : g_needb_s;
    unsigned* sflagb = user ? g_sflagb_u : g_sflagb_s;
    int*  slist      = user ? g_slist_u  : g_slist_s;
    int2* medge      = user ? g_medge_u  : g_medge_s;
    int*  cntS       = &g_cnt[user ? 0 : 1];
    int*  cntE       = &g_cnt[user ? 2 : 3];
    int vb   = user ? blockIdx.x : blockIdx.x - splitBlk;
    int nblk = user ? splitBlk : gridDim.x - splitBlk;

    int tid = vb*blockDim.x + threadIdx.x;
    int l   = threadIdx.x & 31;
    long long stride = (long long)nblk * blockDim.x * 4;

    for (long long i0 = (long long)tid * 4; i0 < E; i0 += stride) {
        int d0=-1, d1=-1, d2=-1, d3=-1;
        if (i0 + 3 < E) {
            int4 dv = *(const int4*)(dst + i0);
            d0 = dv.x; d1 = dv.y; d2 = dv.z; d3 = dv.w;
        } else {
            if (i0     < E) d0 = dst[i0];
            if (i0 + 1 < E) d1 = dst[i0+1];
            if (i0 + 2 < E) d2 = dst[i0+2];
            if (i0 + 3 < E) d3 = dst[i0+3];
        }
        // bitmask gathers: working set ~37KB -> L1-resident
        bool m0 = (d0 >= 0) && ((__ldg(&needb[d0 >> 5]) >> (d0 & 31)) & 1u);
        bool m1 = (d1 >= 0) && ((__ldg(&needb[d1 >> 5]) >> (d1 & 31)) & 1u);
        bool m2 = (d2 >= 0) && ((__ldg(&needb[d2 >> 5]) >> (d2 & 31)) & 1u);
        bool m3 = (d3 >= 0) && ((__ldg(&needb[d3 >> 5]) >> (d3 & 31)) & 1u);
        int mloc = (int)m0 + (int)m1 + (int)m2 + (int)m3;

        // warp inclusive scan + one counter atomic per warp
        int pre = mloc;
        #pragma unroll
        for (int o = 1; o < 32; o <<= 1) {
            int v = __shfl_up_sync(0xffffffffu, pre, o);
            if (l >= o) pre += v;
        }
        int total = __shfl_sync(0xffffffffu, pre, 31);
        int base = 0;
        if (total > 0) {
            if (l == 31) base = atomicAdd(cntE, total);
            base = __shfl_sync(0xffffffffu, base, 31);
        }
        int off = base + pre - mloc;

        if (mloc > 0) {
            int s0=0, s1=0, s2=0, s3=0;
            if (i0 + 3 < E) {
                int4 sv = *(const int4*)(src + i0);
                s0 = sv.x; s1 = sv.y; s2 = sv.z; s3 = sv.w;
            } else {
                if (m0) s0 = src[i0];
                if (m1) s1 = src[i0+1];
                if (m2) s2 = src[i0+2];
                if (m3) s3 = src[i0+3];
            }
            #pragma unroll
            for (int j = 0; j < 4; j++) {
                bool m = (j==0) ? m0 : (j==1) ? m1 : (j==2) ? m2 : m3;
                int  d = (j==0) ? d0 : (j==1) ? d1 : (j==2) ? d2 : d3;
                int  s = (j==0) ? s0 : (j==1) ? s1 : (j==2) ? s2 : s3;
                if (m) {
                    medge[off++] = make_int2(s, d);
                    unsigned bit = 1u << (s & 31);
                    unsigned old = atomicOr(&sflagb[s >> 5], bit);
                    if (!(old & bit))
                        slist[atomicAdd(cntS, 1)] = s;
                }
            }
        }
    }
}

// ---------------- k_h (merged): h = emb@W + el/er for flagged srcs -------------
__global__ void __launch_bounds__(256,4) k_h(const float* __restrict__ uemb,
                                             const float* __restrict__ uW,
                                             const float* __restrict__ ual,
                                             const float* __restrict__ uar,
                                             const float* __restrict__ semb,
                                             const float* __restrict__ sW,
                                             const float* __restrict__ sal,
                                             const float* __restrict__ sar,
                                             int splitBlk) {
    int user = (blockIdx.x < splitBlk);
    const float* emb = user ? uemb : semb;
    const float* W   = user ? uW   : sW;
    const float* al_ = user ? ual  : sal;
    const float* ar_ = user ? uar  : sar;
    float* h  = user ? g_h_u  : g_h_s;
    float* el = user ? g_el_u : g_el_s;
    float* er = user ? g_er_u : g_er_s;
    const int* slist = user ? g_slist_u : g_slist_s;
    int nsrc = g_cnt[user ? 0 : 1];
    int vb = user ? blockIdx.x : blockIdx.x - splitBlk;

    int tile0 = vb * 32;
    if (tile0 >= nsrc) return;

    __shared__ float Ws[DIMK*HD];      // 32 KB
    __shared__ float Es[32][DIMK];     // 8 KB
    __shared__ float als[HD], ars[HD];
    __shared__ int   rows[32];
    int tid = threadIdx.x;

    for (int i = tid; i < DIMK*HD; i += 256) Ws[i] = W[i];
    if (tid < HD) { als[tid] = al_[tid]; ars[tid] = ar_[tid]; }
    if (tid < 32) rows[tid] = (tile0 + tid < nsrc) ? slist[tile0 + tid] : -1;
    __syncthreads();
    for (int idx = tid; idx < 32*DIMK; idx += 256) {
        int r = idx >> 6, k = idx & 63;
        int node = rows[r];
        Es[r][k] = (node >= 0) ? emb[node*DIMK + k] : 0.f;
    }
    __syncthreads();

    int w = tid >> 5, l = tid & 31;
    int r0 = w * 4, c0 = l * 4;
    float acc[4][4] = {};

    for (int k4 = 0; k4 < DIMK; k4 += 4) {
        float4 A0 = *(const float4*)&Es[r0+0][k4];
        float4 A1 = *(const float4*)&Es[r0+1][k4];
        float4 A2 = *(const float4*)&Es[r0+2][k4];
        float4 A3 = *(const float4*)&Es[r0+3][k4];
        #pragma unroll
        for (int kk = 0; kk < 4; kk++) {
            float4 wv = *(const float4*)&Ws[(k4+kk)*HD + c0];
            float e0 = FCMP(A0,kk), e1 = FCMP(A1,kk), e2 = FCMP(A2,kk), e3 = FCMP(A3,kk);
            acc[0][0] += e0*wv.x; acc[0][1] += e0*wv.y; acc[0][2] += e0*wv.z; acc[0][3] += e0*wv.w;
            acc[1][0] += e1*wv.x; acc[1][1] += e1*wv.y; acc[1][2] += e1*wv.z; acc[1][3] += e1*wv.w;
            acc[2][0] += e2*wv.x; acc[2][1] += e2*wv.y; acc[2][2] += e2*wv.z; acc[2][3] += e2*wv.w;
            acc[3][0] += e3*wv.x; acc[3][1] += e3*wv.y; acc[3][2] += e3*wv.z; acc[3][3] += e3*wv.w;
        }
    }

    int head = l >> 4;   // lanes 0-15 head0, 16-31 head1 (c0 = l*4)
    #pragma unroll
    for (int i = 0; i < 4; i++) {
        int node = rows[r0+i];
        if (node >= 0)
            *(float4*)&h[node*HD + c0] = make_float4(acc[i][0], acc[i][1], acc[i][2], acc[i][3]);
        float pl = acc[i][0]*als[c0] + acc[i][1]*als[c0+1] + acc[i][2]*als[c0+2] + acc[i][3]*als[c0+3];
        float pr = acc[i][0]*ars[c0] + acc[i][1]*ars[c0+1] + acc[i][2]*ars[c0+2] + acc[i][3]*ars[c0+3];
        #pragma unroll
        for (int o = 8; o; o >>= 1) {
            pl += __shfl_xor_sync(0xffffffffu, pl, o);
            pr += __shfl_xor_sync(0xffffffffu, pr, o);
        }
        if ((l & 15) == 0 && node >= 0) {
            el[node*NH + head] = pl;
            er[node*NH + head] = pr;
        }
    }
}

// ---------------- k_edge (merged): warp per edge; exp-weighted red.v4 ----------
__global__ void __launch_bounds__(256) k_edge(int splitBlk) {
    int user = (blockIdx.x < splitBlk);
    const int2* me  = user ? g_medge_u : g_medge_s;
    int cnt         = g_cnt[user ? 2 : 3];
    const float* h  = user ? g_h_u  : g_h_s;
    const float* el = user ? g_el_u : g_el_s;
    const float* er = user ? g_er_u : g_er_s;
    float* acc      = user ? g_acc_u : g_acc_s;
    float* den      = user ? g_den_u : g_den_s;
    int vb   = user ? blockIdx.x : blockIdx.x - splitBlk;
    int nblk = user ? splitBlk : gridDim.x - splitBlk;

    int gw = (vb*blockDim.x + threadIdx.x) >> 5;
    int nw = (nblk*blockDim.x) >> 5;
    int l  = threadIdx.x & 31;
    int head = l >> 4;

    for (int e = gw; e < cnt; e += nw) {
        int2 sd = me[e];
        // 4 scattered loads/warp, shfl-broadcast
        float v = 0.f;
        if (l < 2)      v = el[sd.x*NH + l];
        else if (l < 4) v = er[sd.y*NH + (l-2)];
        float elh = __shfl_sync(0xffffffffu, v, head);
        float erh = __shfl_sync(0xffffffffu, v, 2 + head);
        float ev = elh + erh;
        ev = ev > 0.f ? ev : 0.2f * ev;             // leaky_relu(0.2)
        float ex = expf(ev);                        // softmax w/o max-shift (exact ratio)
        float4 hv = *(const float4*)&h[sd.x*HD + l*4];
        red4(&acc[sd.y*HD + l*4], ex*hv.x, ex*hv.y, ex*hv.z, ex*hv.w);
        if ((l & 15) == 0) atomicAdd(&den[sd.y*NH + head], ex);
    }
}

// ---------------- k_gatfin: /den + bias, LN, ELU, head-mean, +emb, build x -----
__device__ __forceinline__ float blockSum128(float v, float* sred) {
    #pragma unroll
    for (int o = 16; o; o >>= 1) v += __shfl_xor_sync(0xffffffffu, v, o);
    __syncthreads();
    if ((threadIdx.x & 31) == 0) sred[threadIdx.x >> 5] = v;
    __syncthreads();
    return sred[0] + sred[1] + sred[2] + sred[3];
}

__global__ void __launch_bounds__(128) k_gatfin(
        const int* __restrict__ uidx, const int* __restrict__ sidx,
        const float* __restrict__ uemb, const float* __restrict__ semb,
        const float* __restrict__ ubias, const float* __restrict__ ulng, const float* __restrict__ ulnb,
        const float* __restrict__ sbias, const float* __restrict__ slng, const float* __restrict__ slnb) {
    __shared__ float sred[4];
    __shared__ float srow[HD];
    int b = blockIdx.x, t = threadIdx.x;
    int u = uidx[b], s = sidx[b];
    float xu = 0.f, xs = 0.f;

    { // user side
        float v = g_acc_u[u*HD + t] / g_den_u[u*NH + (t >> 6)] + ubias[t];
        float mean = blockSum128(v, sred) * (1.f/HD);
        float d = v - mean;
        float var = blockSum128(d*d, sred) * (1.f/HD);
        float nv = d * rsqrtf(var + 1e-5f) * ulng[t] + ulnb[t];
        nv = nv > 0.f ? nv : expm1f(nv);            // ELU
        __syncthreads();
        srow[t] = nv;
        __syncthreads();
        if (t < DIMK) xu = 0.5f*(srow[t] + srow[t+DIMK]) + uemb[u*DIMK + t];
    }
    { // service side
        float v = g_acc_s[s*HD + t] / g_den_s[s*NH + (t >> 6)] + sbias[t];
        float mean = blockSum128(v, sred) * (1.f/HD);
        float d = v - mean;
        float var = blockSum128(d*d, sred) * (1.f/HD);
        float nv = d * rsqrtf(var + 1e-5f) * slng[t] + slnb[t];
        nv = nv > 0.f ? nv : expm1f(nv);
        __syncthreads();
        srow[t] = nv;
        __syncthreads();
        if (t < DIMK) xs = 0.5f*(srow[t] + srow[t+DIMK]) + semb[s*DIMK + t];
    }
    if (t < DIMK) {
        g_x[b*HD + t]        = xu;
        g_x[b*HD + DIMK + t] = xs;
    }
}

// ---------------- k_mlp: fused 128->128->128->1 with LN/relu, sigmoid ----------
__global__ void __launch_bounds__(256) k_mlp(
        const float* __restrict__ W1, const float* __restrict__ b1,
        const float* __restrict__ g1, const float* __restrict__ bb1,
        const float* __restrict__ W2, const float* __restrict__ b2,
        const float* __restrict__ g2, const float* __restrict__ bb2,
        const float* __restrict__ W3, const float* __restrict__ b3,
        float* __restrict__ out) {
    __shared__ float xs[32][HD];       // 16 KB
    __shared__ float Wch[32*HD];       // 16 KB
    int tid = threadIdx.x;
    int rbase = blockIdx.x * 32;
    int w = tid >> 5, l = tid & 31;
    int r0 = w * 4, c0 = l * 4;

    for (int i = tid; i < 32*HD; i += 256) ((float*)xs)[i] = g_x[rbase*HD + i];

    const float* Wp[2]  = {W1, W2};
    const float* bp[2]  = {b1, b2};
    const float* gp[2]  = {g1, g2};
    const float* bbp[2] = {bb1, bb2};
    float val[4][4];

    for (int layer = 0; layer < 2; layer++) {
        float acc[4][4] = {};
        for (int kc = 0; kc < 4; kc++) {
            __syncthreads();
            for (int i = tid; i < 32*HD; i += 256) Wch[i] = Wp[layer][kc*32*HD + i];
            __syncthreads();
            #pragma unroll
            for (int k4 = 0; k4 < 32; k4 += 4) {
                float4 A0 = *(const float4*)&xs[r0+0][kc*32 + k4];
                float4 A1 = *(const float4*)&xs[r0+1][kc*32 + k4];
                float4 A2 = *(const float4*)&xs[r0+2][kc*32 + k4];
                float4 A3 = *(const float4*)&xs[r0+3][kc*32 + k4];
                #pragma unroll
                for (int kk = 0; kk < 4; kk++) {
                    float4 wv = *(const float4*)&Wch[(k4+kk)*HD + c0];
                    float e0 = FCMP(A0,kk), e1 = FCMP(A1,kk), e2 = FCMP(A2,kk), e3 = FCMP(A3,kk);
                    acc[0][0] += e0*wv.x; acc[0][1] += e0*wv.y; acc[0][2] += e0*wv.z; acc[0][3] += e0*wv.w;
                    acc[1][0] += e1*wv.x; acc[1][1] += e1*wv.y; acc[1][2] += e1*wv.z; acc[1][3] += e1*wv.w;
                    acc[2][0] += e2*wv.x; acc[2][1] += e2*wv.y; acc[2][2] += e2*wv.z; acc[2][3] += e2*wv.w;
                    acc[3][0] += e3*wv.x; acc[3][1] += e3*wv.y; acc[3][2] += e3*wv.z; acc[3][3] += e3*wv.w;
                }
            }
        }
        __syncthreads();   // all GEMM reads of xs complete before overwrite

        float4 bv  = *(const float4*)&bp[layer][c0];
        float4 gv  = *(const float4*)&gp[layer][c0];
        float4 bbv = *(const float4*)&bbp[layer][c0];
        #pragma unroll
        for (int i = 0; i < 4; i++) {
            float a0 = acc[i][0] + bv.x, a1 = acc[i][1] + bv.y;
            float a2 = acc[i][2] + bv.z, a3 = acc[i][3] + bv.w;
            float sum = a0 + a1 + a2 + a3;
            #pragma unroll
            for (int o = 16; o; o >>= 1) sum += __shfl_xor_sync(0xffffffffu, sum, o);
            float mean = sum * (1.f/HD);
            float d0 = a0-mean, d1 = a1-mean, d2 = a2-mean, d3 = a3-mean;
            float sq = d0*d0 + d1*d1 + d2*d2 + d3*d3;
            #pragma unroll
            for (int o = 16; o; o >>= 1) sq += __shfl_xor_sync(0xffffffffu, sq, o);
            float rstd = rsqrtf(sq * (1.f/HD) + 1e-5f);
            float v0 = fmaxf(d0*rstd*gv.x + bbv.x, 0.f);
            float v1 = fmaxf(d1*rstd*gv.y + bbv.y, 0.f);
            float v2 = fmaxf(d2*rstd*gv.z + bbv.z, 0.f);
            float v3 = fmaxf(d3*rstd*gv.w + bbv.w, 0.f);
            xs[r0+i][c0+0] = v0; xs[r0+i][c0+1] = v1;
            xs[r0+i][c0+2] = v2; xs[r0+i][c0+3] = v3;
            val[i][0] = v0; val[i][1] = v1; val[i][2] = v2; val[i][3] = v3;
        }
    }

    float4 w3 = *(const float4*)&W3[c0];
    float bias3 = b3[0];
    #pragma unroll
    for (int i = 0; i < 4; i++) {
        float p = val[i][0]*w3.x + val[i][1]*w3.y + val[i][2]*w3.z + val[i][3]*w3.w;
        #pragma unroll
        for (int o = 16; o; o >>= 1) p += __shfl_xor_sync(0xffffffffu, p, o);
        if (l == 0) out[rbase + r0 + i] = 1.f / (1.f + __expf(-(p + bias3)));
    }
}

// ---------------- launch --------------------------------------------------------
extern "C" void kernel_launch(void* const* d_in, const int* in_sizes, int n_in,
                              void* d_out, int out_size) {
    const int*   uidx  = (const int*)  d_in[0];
    const int*   sidx  = (const int*)  d_in[1];
    const int*   usrc  = (const int*)  d_in[2];
    const int*   udst  = (const int*)  d_in[3];
    const int*   ssrc  = (const int*)  d_in[4];
    const int*   sdst  = (const int*)  d_in[5];
    const float* uemb  = (const float*)d_in[6];
    const float* semb  = (const float*)d_in[7];
    const float* uW    = (const float*)d_in[8];
    const float* ual   = (const float*)d_in[9];
    const float* uar   = (const float*)d_in[10];
    const float* ubias = (const float*)d_in[11];
    const float* ulng  = (const float*)d_in[12];
    const float* ulnb  = (const float*)d_in[13];
    const float* sW    = (const float*)d_in[14];
    const float* sal   = (const float*)d_in[15];
    const float* sar   = (const float*)d_in[16];
    const float* sbias = (const float*)d_in[17];
    const float* slng  = (const float*)d_in[18];
    const float* slnb  = (const float*)d_in[19];
    const float* W1    = (const float*)d_in[20];
    const float* b1    = (const float*)d_in[21];
    const float* g1    = (const float*)d_in[22];
    const float* bb1   = (const float*)d_in[23];
    const float* W2    = (const float*)d_in[24];
    const float* b2    = (const float*)d_in[25];
    const float* g2    = (const float*)d_in[26];
    const float* bb2   = (const float*)d_in[27];
    const float* W3    = (const float*)d_in[28];
    const float* b3    = (const float*)d_in[29];
    float* out = (float*)d_out;

    int B  = in_sizes[0];
    int Eu = in_sizes[2];
    int Es = in_sizes[4];

    k_zero<<<64, 256>>>();
    k_mark<<<B, 128>>>(uidx, sidx);
    {
        int gu = (Eu/4 + 255) / 256;            // ~880
        int gs = (Es/4 + 255) / 256;            // ~1758
        k_compact<<<gu + gs, 256>>>(usrc, udst, Eu, ssrc, sdst, Es, gu);
    }
    {
        int hu = (NU + 31) / 32;                // 3125
        int hs = (NS + 31) / 32;                // 6250
        k_h<<<hu + hs, 256>>>(uemb, uW, ual, uar, semb, sW, sal, sar, hu);
    }
    k_edge<<<2368, 256>>>(1184);
    k_gatfin<<<B, 128>>>(uidx, sidx, uemb, semb, ubias, ulng, ulnb, sbias, slng, slnb);
    k_mlp<<<B/32, 256>>>(W1, b1, g1, bb1, W2, b2, g2, bb2, W3, b3, out);
}

// round 5
// speedup vs baseline: 1.6895x; 1.6895x over previous
#include <cuda_runtime.h>
#include <math.h>

#define NU 100000
#define NS 200000
#define DIMK 64
#define NH 2
#define HD 128          // NH * DIMK
#define EU (NU*9)
#define ESZ (NS*9)
#define BMAX 16384
#define NUW ((NU+31)/32)
#define NSW ((NS+31)/32)

// ---------------- scratch (static device globals) -------------------------------
__device__ float g_acc_u[NU*HD];     // per-dst: sum ex * emb[src]  (head-major)
__device__ float g_acc_s[NS*HD];
__device__ float g_den_u[NU*NH];
__device__ float g_den_s[NS*NH];
__device__ float g_el_u[NU*NH];      // interleaved [node*2+h]
__device__ float g_er_u[NU*NH];
__device__ float g_el_s[NS*NH];
__device__ float g_er_s[NS*NH];
__device__ float g_wl_u[DIMK*NH];    // W @ a_l folded vectors, [k*2+h]
__device__ float g_wr_u[DIMK*NH];
__device__ float g_wl_s[DIMK*NH];
__device__ float g_wr_s[DIMK*NH];
__device__ unsigned g_needb_u[NUW];
__device__ unsigned g_needb_s[NSW];
__device__ unsigned g_sflagb_u[NUW];
__device__ unsigned g_sflagb_s[NSW];
__device__ int   g_slist_u[NU];
__device__ int   g_slist_s[NS];
__device__ int2  g_medge_u[EU];
__device__ int2  g_medge_s[ESZ];
__device__ int   g_cnt[4];   // [0]=nsrc_u [1]=nsrc_s [2]=nedge_u [3]=nedge_s
__device__ float g_x[BMAX*HD];

// ---------------- helpers ------------------------------------------------------
__device__ __forceinline__ void red4(float* p, float a, float b, float c, float d) {
    asm volatile("{ .reg .u64 q; cvta.to.global.u64 q, %0;"
                 "  red.global.add.v4.f32 [q], {%1, %2, %3, %4}; }"
                 :: "l"(p), "f"(a), "f"(b), "f"(c), "f"(d) : "memory");
}

#define FCMP(v,kk) ((kk)==0?(v).x:((kk)==1?(v).y:((kk)==2?(v).z:(v).w)))

// ---------------- k_zero: reset bitmasks + counters ----------------------------
__global__ void k_zero() {
    int i = blockIdx.x*blockDim.x + threadIdx.x;
    int st = gridDim.x*blockDim.x;
    for (int j = i; j < NUW; j += st) { g_needb_u[j] = 0u; g_sflagb_u[j] = 0u; }
    for (int j = i; j < NSW; j += st) { g_needb_s[j] = 0u; g_sflagb_s[j] = 0u; }
    if (i < 4) g_cnt[i] = 0;
}

// ---------------- k_wvec: fold attention vectors through W --------------------
// wl[k,h] = sum_d W[k, h*64+d] * al[h,d]   (and same for wr/ar)
__global__ void __launch_bounds__(256) k_wvec(const float* __restrict__ uW,
                                              const float* __restrict__ ual,
                                              const float* __restrict__ uar,
                                              const float* __restrict__ sW,
                                              const float* __restrict__ sal,
                                              const float* __restrict__ sar) {
    int tid = threadIdx.x;            // 0..255
    int user = tid < 128;
    int t = tid & 127;
    int k = t >> 1, h = t & 1;
    const float* W  = user ? uW  : sW;
    const float* al = user ? ual : sal;
    const float* ar = user ? uar : sar;
    float accl = 0.f, accr = 0.f;
    #pragma unroll 8
    for (int d = 0; d < DIMK; d++) {
        float w = W[k*HD + h*DIMK + d];
        accl += w * al[h*DIMK + d];
        accr += w * ar[h*DIMK + d];
    }
    if (user) { g_wl_u[k*2+h] = accl; g_wr_u[k*2+h] = accr; }
    else      { g_wl_s[k*2+h] = accl; g_wr_s[k*2+h] = accr; }
}

// ---------------- k_mark: mark needed dsts (bits), zero their acc/den rows -----
__global__ void __launch_bounds__(128) k_mark(const int* __restrict__ uidx,
                                              const int* __restrict__ sidx) {
    int b = blockIdx.x, t = threadIdx.x;
    int u = uidx[b], s = sidx[b];
    g_acc_u[u*HD + t] = 0.f;
    g_acc_s[s*HD + t] = 0.f;
    if (t < NH) { g_den_u[u*NH + t] = 0.f; g_den_s[s*NH + t] = 0.f; }
    if (t == 0) {
        atomicOr(&g_needb_u[u >> 5], 1u << (u & 31));
        atomicOr(&g_needb_s[s >> 5], 1u << (s & 31));
    }
}

// ---------------- k_compact (merged): filter edges by needed dst; dedupe srcs --
__global__ void __launch_bounds__(256) k_compact(const int* __restrict__ usrc,
                                                 const int* __restrict__ udst, int Eu,
                                                 const int* __restrict__ ssrc,
                                                 const int* __restrict__ sdst, int Es,
                                                 int splitBlk) {
    int user = (blockIdx.x < splitBlk);
    const int* __restrict__ src = user ? usrc : ssrc;
    const int* __restrict__ dst = user ? udst : sdst;
    int E = user ? Eu : Es;
    const unsigned* __restrict__ needb = user ? g_needb_u : g_needb_s;
    unsigned* sflagb = user ? g_sflagb_u : g_sflagb_s;
    int*  slist      = user ? g_slist_u  : g_slist_s;
    int2* medge      = user ? g_medge_u  : g_medge_s;
    int*  cntS       = &g_cnt[user ? 0 : 1];
    int*  cntE       = &g_cnt[user ? 2 : 3];
    int vb   = user ? blockIdx.x : blockIdx.x - splitBlk;
    int nblk = user ? splitBlk : gridDim.x - splitBlk;

    int tid = vb*blockDim.x + threadIdx.x;
    int l   = threadIdx.x & 31;
    long long stride = (long long)nblk * blockDim.x * 4;

    for (long long i0 = (long long)tid * 4; i0 < E; i0 += stride) {
        int d0=-1, d1=-1, d2=-1, d3=-1;
        if (i0 + 3 < E) {
            int4 dv = *(const int4*)(dst + i0);
            d0 = dv.x; d1 = dv.y; d2 = dv.z; d3 = dv.w;
        } else {
            if (i0     < E) d0 = dst[i0];
            if (i0 + 1 < E) d1 = dst[i0+1];
            if (i0 + 2 < E) d2 = dst[i0+2];
            if (i0 + 3 < E) d3 = dst[i0+3];
        }
        bool m0 = (d0 >= 0) && ((__ldg(&needb[d0 >> 5]) >> (d0 & 31)) & 1u);
        bool m1 = (d1 >= 0) && ((__ldg(&needb[d1 >> 5]) >> (d1 & 31)) & 1u);
        bool m2 = (d2 >= 0) && ((__ldg(&needb[d2 >> 5]) >> (d2 & 31)) & 1u);
        bool m3 = (d3 >= 0) && ((__ldg(&needb[d3 >> 5]) >> (d3 & 31)) & 1u);
        int mloc = (int)m0 + (int)m1 + (int)m2 + (int)m3;

        int pre = mloc;
        #pragma unroll
        for (int o = 1; o < 32; o <<= 1) {
            int v = __shfl_up_sync(0xffffffffu, pre, o);
            if (l >= o) pre += v;
        }
        int total = __shfl_sync(0xffffffffu, pre, 31);
        int base = 0;
        if (total > 0) {
            if (l == 31) base = atomicAdd(cntE, total);
            base = __shfl_sync(0xffffffffu, base, 31);
        }
        int off = base + pre - mloc;

        if (mloc > 0) {
            int s0=0, s1=0, s2=0, s3=0;
            if (i0 + 3 < E) {
                int4 sv = *(const int4*)(src + i0);
                s0 = sv.x; s1 = sv.y; s2 = sv.z; s3 = sv.w;
            } else {
                if (m0) s0 = src[i0];
                if (m1) s1 = src[i0+1];
                if (m2) s2 = src[i0+2];
                if (m3) s3 = src[i0+3];
            }
            #pragma unroll
            for (int j = 0; j < 4; j++) {
                bool m = (j==0) ? m0 : (j==1) ? m1 : (j==2) ? m2 : m3;
                int  d = (j==0) ? d0 : (j==1) ? d1 : (j==2) ? d2 : d3;
                int  s = (j==0) ? s0 : (j==1) ? s1 : (j==2) ? s2 : s3;
                if (m) {
                    medge[off++] = make_int2(s, d);
                    unsigned bit = 1u << (s & 31);
                    unsigned old = atomicOr(&sflagb[s >> 5], bit);
                    if (!(old & bit))
                        slist[atomicAdd(cntS, 1)] = s;
                }
            }
        }
    }
}

// ---------------- k_el (merged): el/er dots for flagged srcs -------------------
// el[n,h] = emb[n] . wl[:,h]; er[n,h] = emb[n] . wr[:,h]
// (every needed dst has a self-loop, so dsts are always in the flagged set)
__global__ void __launch_bounds__(256) k_el(const float* __restrict__ uemb,
                                            const float* __restrict__ semb,
                                            int splitBlk) {
    int user = (blockIdx.x < splitBlk);
    const float* emb = user ? uemb : semb;
    const float* wl  = user ? g_wl_u : g_wl_s;
    const float* wr  = user ? g_wr_u : g_wr_s;
    float* el = user ? g_el_u : g_el_s;
    float* er = user ? g_er_u : g_er_s;
    const int* slist = user ? g_slist_u : g_slist_s;
    int nsrc = g_cnt[user ? 0 : 1];
    int vb   = user ? blockIdx.x : blockIdx.x - splitBlk;
    int nblk = user ? splitBlk : gridDim.x - splitBlk;

    __shared__ float swl[DIMK*NH], swr[DIMK*NH];
    if (threadIdx.x < DIMK*NH) { swl[threadIdx.x] = wl[threadIdx.x]; swr[threadIdx.x] = wr[threadIdx.x]; }
    __syncthreads();

    int stride = nblk * blockDim.x;
    for (int i = vb*blockDim.x + threadIdx.x; i < nsrc; i += stride) {
        int node = slist[i];
        const float* e = emb + (long long)node * DIMK;
        float el0=0.f, el1=0.f, er0=0.f, er1=0.f;
        #pragma unroll
        for (int k4 = 0; k4 < DIMK; k4 += 4) {
            float4 ev = *(const float4*)(e + k4);
            #pragma unroll
            for (int kk = 0; kk < 4; kk++) {
                float x = FCMP(ev, kk);
                el0 += x * swl[(k4+kk)*2 + 0];
                el1 += x * swl[(k4+kk)*2 + 1];
                er0 += x * swr[(k4+kk)*2 + 0];
                er1 += x * swr[(k4+kk)*2 + 1];
            }
        }
        el[node*NH + 0] = el0; el[node*NH + 1] = el1;
        er[node*NH + 0] = er0; er[node*NH + 1] = er1;
    }
}

// ---------------- k_edge (merged): warp per edge; acc += ex * emb[src] ---------
__global__ void __launch_bounds__(256) k_edge(const float* __restrict__ uemb,
                                              const float* __restrict__ semb,
                                              int splitBlk) {
    int user = (blockIdx.x < splitBlk);
    const int2* me  = user ? g_medge_u : g_medge_s;
    int cnt         = g_cnt[user ? 2 : 3];
    const float* emb = user ? uemb : semb;
    const float* el = user ? g_el_u : g_el_s;
    const float* er = user ? g_er_u : g_er_s;
    float* acc      = user ? g_acc_u : g_acc_s;
    float* den      = user ? g_den_u : g_den_s;
    int vb   = user ? blockIdx.x : blockIdx.x - splitBlk;
    int nblk = user ? splitBlk : gridDim.x - splitBlk;

    int gw = (vb*blockDim.x + threadIdx.x) >> 5;
    int nw = (nblk*blockDim.x) >> 5;
    int l  = threadIdx.x & 31;
    int head = l >> 4;
    int d0 = (l & 15) * 4;

    for (int e = gw; e < cnt; e += nw) {
        int2 sd = me[e];
        float v = 0.f;
        if (l < 2)      v = el[sd.x*NH + l];
        else if (l < 4) v = er[sd.y*NH + (l-2)];
        float elh = __shfl_sync(0xffffffffu, v, head);
        float erh = __shfl_sync(0xffffffffu, v, 2 + head);
        float ev = elh + erh;
        ev = ev > 0.f ? ev : 0.2f * ev;             // leaky_relu(0.2)
        float ex = __expf(ev);                      // softmax w/o max-shift (exact ratio)
        float4 hv = *(const float4*)&emb[(long long)sd.x*DIMK + d0];
        red4(&acc[sd.y*HD + head*DIMK + d0], ex*hv.x, ex*hv.y, ex*hv.z, ex*hv.w);
        if ((l & 15) == 0) atomicAdd(&den[sd.y*NH + head], ex);
    }
}

// ---------------- k_gatfin: (acc/den)@W_head + bias, LN, ELU, head-mean, +emb --
__device__ __forceinline__ float blockSum128(float v, float* sred) {
    #pragma unroll
    for (int o = 16; o; o >>= 1) v += __shfl_xor_sync(0xffffffffu, v, o);
    __syncthreads();
    if ((threadIdx.x & 31) == 0) sred[threadIdx.x >> 5] = v;
    __syncthreads();
    return sred[0] + sred[1] + sred[2] + sred[3];
}

__global__ void __launch_bounds__(128) k_gatfin(
        const int* __restrict__ uidx, const int* __restrict__ sidx,
        const float* __restrict__ uemb, const float* __restrict__ semb,
        const float* __restrict__ uW, const float* __restrict__ sW,
        const float* __restrict__ ubias, const float* __restrict__ ulng, const float* __restrict__ ulnb,
        const float* __restrict__ sbias, const float* __restrict__ slng, const float* __restrict__ slnb) {
    __shared__ float sred[4];
    __shared__ float srow[HD];
    __shared__ float agg[HD];
    int b = blockIdx.x, t = threadIdx.x;
    int u = uidx[b], s = sidx[b];
    int h = t >> 6;                   // head for this output column
    float xu = 0.f, xs = 0.f;

    { // user side
        agg[t] = g_acc_u[u*HD + t] / g_den_u[u*NH + h];
        __syncthreads();
        float v = ubias[t];
        #pragma unroll 4
        for (int k = 0; k < DIMK; k++)
            v += agg[h*DIMK + k] * __ldg(&uW[k*HD + t]);
        float mean = blockSum128(v, sred) * (1.f/HD);
        float d = v - mean;
        float var = blockSum128(d*d, sred) * (1.f/HD);
        float nv = d * rsqrtf(var + 1e-5f) * ulng[t] + ulnb[t];
        nv = nv > 0.f ? nv : expm1f(nv);            // ELU
        __syncthreads();
        srow[t] = nv;
        __syncthreads();
        if (t < DIMK) xu = 0.5f*(srow[t] + srow[t+DIMK]) + uemb[u*DIMK + t];
        __syncthreads();
    }
    { // service side
        agg[t] = g_acc_s[s*HD + t] / g_den_s[s*NH + h];
        __syncthreads();
        float v = sbias[t];
        #pragma unroll 4
        for (int k = 0; k < DIMK; k++)
            v += agg[h*DIMK + k] * __ldg(&sW[k*HD + t]);
        float mean = blockSum128(v, sred) * (1.f/HD);
        float d = v - mean;
        float var = blockSum128(d*d, sred) * (1.f/HD);
        float nv = d * rsqrtf(var + 1e-5f) * slng[t] + slnb[t];
        nv = nv > 0.f ? nv : expm1f(nv);
        __syncthreads();
        srow[t] = nv;
        __syncthreads();
        if (t < DIMK) xs = 0.5f*(srow[t] + srow[t+DIMK]) + semb[s*DIMK + t];
    }
    if (t < DIMK) {
        g_x[b*HD + t]        = xu;
        g_x[b*HD + DIMK + t] = xs;
    }
}

// ---------------- k_mlp: fused 128->128->128->1 with LN/relu, sigmoid ----------
__global__ void __launch_bounds__(256) k_mlp(
        const float* __restrict__ W1, const float* __restrict__ b1,
        const float* __restrict__ g1, const float* __restrict__ bb1,
        const float* __restrict__ W2, const float* __restrict__ b2,
        const float* __restrict__ g2, const float* __restrict__ bb2,
        const float* __restrict__ W3, const float* __restrict__ b3,
        float* __restrict__ out) {
    __shared__ float xs[32][HD];       // 16 KB
    __shared__ float Wch[32*HD];       // 16 KB
    int tid = threadIdx.x;
    int rbase = blockIdx.x * 32;
    int w = tid >> 5, l = tid & 31;
    int r0 = w * 4, c0 = l * 4;

    for (int i = tid; i < 32*HD; i += 256) ((float*)xs)[i] = g_x[rbase*HD + i];

    const float* Wp[2]  = {W1, W2};
    const float* bp[2]  = {b1, b2};
    const float* gp[2]  = {g1, g2};
    const float* bbp[2] = {bb1, bb2};
    float val[4][4];

    for (int layer = 0; layer < 2; layer++) {
        float acc[4][4] = {};
        for (int kc = 0; kc < 4; kc++) {
            __syncthreads();
            for (int i = tid; i < 32*HD; i += 256) Wch[i] = Wp[layer][kc*32*HD + i];
            __syncthreads();
            #pragma unroll
            for (int k4 = 0; k4 < 32; k4 += 4) {
                float4 A0 = *(const float4*)&xs[r0+0][kc*32 + k4];
                float4 A1 = *(const float4*)&xs[r0+1][kc*32 + k4];
                float4 A2 = *(const float4*)&xs[r0+2][kc*32 + k4];
                float4 A3 = *(const float4*)&xs[r0+3][kc*32 + k4];
                #pragma unroll
                for (int kk = 0; kk < 4; kk++) {
                    float4 wv = *(const float4*)&Wch[(k4+kk)*HD + c0];
                    float e0 = FCMP(A0,kk), e1 = FCMP(A1,kk), e2 = FCMP(A2,kk), e3 = FCMP(A3,kk);
                    acc[0][0] += e0*wv.x; acc[0][1] += e0*wv.y; acc[0][2] += e0*wv.z; acc[0][3] += e0*wv.w;
                    acc[1][0] += e1*wv.x; acc[1][1] += e1*wv.y; acc[1][2] += e1*wv.z; acc[1][3] += e1*wv.w;
                    acc[2][0] += e2*wv.x; acc[2][1] += e2*wv.y; acc[2][2] += e2*wv.z; acc[2][3] += e2*wv.w;
                    acc[3][0] += e3*wv.x; acc[3][1] += e3*wv.y; acc[3][2] += e3*wv.z; acc[3][3] += e3*wv.w;
                }
            }
        }
        __syncthreads();

        float4 bv  = *(const float4*)&bp[layer][c0];
        float4 gv  = *(const float4*)&gp[layer][c0];
        float4 bbv = *(const float4*)&bbp[layer][c0];
        #pragma unroll
        for (int i = 0; i < 4; i++) {
            float a0 = acc[i][0] + bv.x, a1 = acc[i][1] + bv.y;
            float a2 = acc[i][2] + bv.z, a3 = acc[i][3] + bv.w;
            float sum = a0 + a1 + a2 + a3;
            #pragma unroll
            for (int o = 16; o; o >>= 1) sum += __shfl_xor_sync(0xffffffffu, sum, o);
            float mean = sum * (1.f/HD);
            float d0 = a0-mean, d1 = a1-mean, d2 = a2-mean, d3 = a3-mean;
            float sq = d0*d0 + d1*d1 + d2*d2 + d3*d3;
            #pragma unroll
            for (int o = 16; o; o >>= 1) sq += __shfl_xor_sync(0xffffffffu, sq, o);
            float rstd = rsqrtf(sq * (1.f/HD) + 1e-5f);
            float v0 = fmaxf(d0*rstd*gv.x + bbv.x, 0.f);
            float v1 = fmaxf(d1*rstd*gv.y + bbv.y, 0.f);
            float v2 = fmaxf(d2*rstd*gv.z + bbv.z, 0.f);
            float v3 = fmaxf(d3*rstd*gv.w + bbv.w, 0.f);
            xs[r0+i][c0+0] = v0; xs[r0+i][c0+1] = v1;
            xs[r0+i][c0+2] = v2; xs[r0+i][c0+3] = v3;
            val[i][0] = v0; val[i][1] = v1; val[i][2] = v2; val[i][3] = v3;
        }
    }

    float4 w3 = *(const float4*)&W3[c0];
    float bias3 = b3[0];
    #pragma unroll
    for (int i = 0; i < 4; i++) {
        float p = val[i][0]*w3.x + val[i][1]*w3.y + val[i][2]*w3.z + val[i][3]*w3.w;
        #pragma unroll
        for (int o = 16; o; o >>= 1) p += __shfl_xor_sync(0xffffffffu, p, o);
        if (l == 0) out[rbase + r0 + i] = 1.f / (1.f + __expf(-(p + bias3)));
    }
}

// ---------------- launch --------------------------------------------------------
extern "C" void kernel_launch(void* const* d_in, const int* in_sizes, int n_in,
                              void* d_out, int out_size) {
    const int*   uidx  = (const int*)  d_in[0];
    const int*   sidx  = (const int*)  d_in[1];
    const int*   usrc  = (const int*)  d_in[2];
    const int*   udst  = (const int*)  d_in[3];
    const int*   ssrc  = (const int*)  d_in[4];
    const int*   sdst  = (const int*)  d_in[5];
    const float* uemb  = (const float*)d_in[6];
    const float* semb  = (const float*)d_in[7];
    const float* uW    = (const float*)d_in[8];
    const float* ual   = (const float*)d_in[9];
    const float* uar   = (const float*)d_in[10];
    const float* ubias = (const float*)d_in[11];
    const float* ulng  = (const float*)d_in[12];
    const float* ulnb  = (const float*)d_in[13];
    const float* sW    = (const float*)d_in[14];
    const float* sal   = (const float*)d_in[15];
    const float* sar   = (const float*)d_in[16];
    const float* sbias = (const float*)d_in[17];
    const float* slng  = (const float*)d_in[18];
    const float* slnb  = (const float*)d_in[19];
    const float* W1    = (const float*)d_in[20];
    const float* b1    = (const float*)d_in[21];
    const float* g1    = (const float*)d_in[22];
    const float* bb1   = (const float*)d_in[23];
    const float* W2    = (const float*)d_in[24];
    const float* b2    = (const float*)d_in[25];
    const float* g2    = (const float*)d_in[26];
    const float* bb2   = (const float*)d_in[27];
    const float* W3    = (const float*)d_in[28];
    const float* b3    = (const float*)d_in[29];
    float* out = (float*)d_out;

    int B  = in_sizes[0];
    int Eu = in_sizes[2];
    int Es = in_sizes[4];

    k_zero<<<64, 256>>>();
    k_wvec<<<1, 256>>>(uW, ual, uar, sW, sal, sar);
    k_mark<<<B, 128>>>(uidx, sidx);
    {
        int gu = (Eu/4 + 255) / 256;            // ~880
        int gs = (Es/4 + 255) / 256;            // ~1758
        k_compact<<<gu + gs, 256>>>(usrc, udst, Eu, ssrc, sdst, Es, gu);
    }
    {
        int eu = (NU + 255) / 256;              // 391
        int es = (NS + 255) / 256;              // 782
        k_el<<<eu + es, 256>>>(uemb, semb, eu);
    }
    k_edge<<<2368, 256>>>(uemb, semb, 1184);
    k_gatfin<<<B, 128>>>(uidx, sidx, uemb, semb, uW, sW,
                         ubias, ulng, ulnb, sbias, slng, slnb);
    k_mlp<<<B/32, 256>>>(W1, b1, g1, bb1, W2, b2, g2, bb2, W3, b3, out);
}

// round 6
// speedup vs baseline: 2.2087x; 1.3073x over previous
#include <cuda_runtime.h>
#include <math.h>

#define NU 100000
#define NS 200000
#define DIMK 64
#define NH 2
#define HD 128          // NH * DIMK
#define BMAX 16384
#define NUW ((NU+31)/32)
#define NSW ((NS+31)/32)

// ---------------- scratch (static device globals) -------------------------------
__device__ float g_acc_u[NU*HD];     // per-dst: sum ex * emb[src]  (head-major)
__device__ float g_acc_s[NS*HD];
__device__ float g_den_u[NU*NH];
__device__ float g_den_s[NS*NH];
__device__ float g_er_u[NU*NH];      // er for needed dsts, [node*2+h]
__device__ float g_er_s[NS*NH];
__device__ float g_wl_u[DIMK*NH];    // W @ a_l folded vectors, [k*2+h]
__device__ float g_wr_u[DIMK*NH];
__device__ float g_wl_s[DIMK*NH];
__device__ float g_wr_s[DIMK*NH];
__device__ unsigned g_needb_u[NUW];
__device__ unsigned g_needb_s[NSW];
__device__ float g_x[BMAX*HD];

// ---------------- helpers ------------------------------------------------------
__device__ __forceinline__ void red4(float* p, float a, float b, float c, float d) {
    asm volatile("{ .reg .u64 q; cvta.to.global.u64 q, %0;"
                 "  red.global.add.v4.f32 [q], {%1, %2, %3, %4}; }"
                 :: "l"(p), "f"(a), "f"(b), "f"(c), "f"(d) : "memory");
}

#define FCMP(v,kk) ((kk)==0?(v).x:((kk)==1?(v).y:((kk)==2?(v).z:(v).w)))

// ---------------- k_zero: reset need bitmasks ----------------------------------
__global__ void k_zero() {
    int i = blockIdx.x*blockDim.x + threadIdx.x;
    int st = gridDim.x*blockDim.x;
    for (int j = i; j < NUW; j += st) g_needb_u[j] = 0u;
    for (int j = i; j < NSW; j += st) g_needb_s[j] = 0u;
}

// ---------------- k_wvec: fold attention vectors through W --------------------
// wl[k,h] = sum_d W[k, h*64+d] * al[h,d]   (and same for wr/ar)
__global__ void __launch_bounds__(256) k_wvec(const float* __restrict__ uW,
                                              const float* __restrict__ ual,
                                              const float* __restrict__ uar,
                                              const float* __restrict__ sW,
                                              const float* __restrict__ sal,
                                              const float* __restrict__ sar) {
    int tid = threadIdx.x;            // 0..255
    int user = tid < 128;
    int t = tid & 127;
    int k = t >> 1, h = t & 1;
    const float* W  = user ? uW  : sW;
    const float* al = user ? ual : sal;
    const float* ar = user ? uar : sar;
    float accl = 0.f, accr = 0.f;
    #pragma unroll 8
    for (int d = 0; d < DIMK; d++) {
        float w = W[k*HD + h*DIMK + d];
        accl += w * al[h*DIMK + d];
        accr += w * ar[h*DIMK + d];
    }
    if (user) { g_wl_u[k*2+h] = accl; g_wr_u[k*2+h] = accr; }
    else      { g_wl_s[k*2+h] = accl; g_wr_s[k*2+h] = accr; }
}

// ---------------- k_mark: mark bits, zero acc/den, compute er for dsts ---------
__global__ void __launch_bounds__(128) k_mark(const int* __restrict__ uidx,
                                              const int* __restrict__ sidx,
                                              const float* __restrict__ uemb,
                                              const float* __restrict__ semb) {
    int b = blockIdx.x, t = threadIdx.x;
    int u = uidx[b], s = sidx[b];
    g_acc_u[u*HD + t] = 0.f;
    g_acc_s[s*HD + t] = 0.f;
    if (t < NH) { g_den_u[u*NH + t] = 0.f; g_den_s[s*NH + t] = 0.f; }
    if (t == 0) {
        atomicOr(&g_needb_u[u >> 5], 1u << (u & 31));
        atomicOr(&g_needb_s[s >> 5], 1u << (s & 31));
    }
    // er[d,h] = emb[d] . wr[:,h]; one warp per (side, head); duplicate dsts
    // recompute the same value (benign).
    {
        int wid = t >> 5, l = t & 31;
        int user = wid < 2, head = wid & 1;
        int node = user ? u : s;
        const float* emb = user ? uemb : semb;
        const float* wr  = user ? g_wr_u : g_wr_s;
        float* er        = user ? g_er_u : g_er_s;
        int k2 = l * 2;
        float2 ev = *(const float2*)&emb[(long long)node*DIMK + k2];
        float p = ev.x * __ldg(&wr[k2*2 + head]) + ev.y * __ldg(&wr[(k2+1)*2 + head]);
        #pragma unroll
        for (int o = 16; o; o >>= 1) p += __shfl_xor_sync(0xffffffffu, p, o);
        if (l == 0) er[node*NH + head] = p;
    }
}

// ---------------- k_edge_all: fused filter + attention + aggregate -------------
// Streams raw edge lists; matched edges go through a per-block smem queue and
// are drained warp-per-edge (el computed inline from emb[src]).
__global__ void __launch_bounds__(256) k_edge_all(const int* __restrict__ usrc,
                                                  const int* __restrict__ udst, int Eu,
                                                  const int* __restrict__ ssrc,
                                                  const int* __restrict__ sdst, int Es,
                                                  const float* __restrict__ uemb,
                                                  const float* __restrict__ semb,
                                                  int splitBlk) {
    int user = (blockIdx.x < splitBlk);
    const int* __restrict__ src = user ? usrc : ssrc;
    const int* __restrict__ dst = user ? udst : sdst;
    int E = user ? Eu : Es;
    const unsigned* __restrict__ needb = user ? g_needb_u : g_needb_s;
    const float* __restrict__ emb = user ? uemb : semb;
    const float* __restrict__ wl  = user ? g_wl_u : g_wl_s;
    const float* __restrict__ er  = user ? g_er_u : g_er_s;
    float* acc = user ? g_acc_u : g_acc_s;
    float* den = user ? g_den_u : g_den_s;
    int vb   = user ? blockIdx.x : blockIdx.x - splitBlk;
    int nblk = user ? splitBlk : gridDim.x - splitBlk;

    __shared__ int2 q[256];
    __shared__ int  qcnt;

    int tid = threadIdx.x;
    int wid = tid >> 5, l = tid & 31;
    int head = l >> 4;
    int lq = (l & 15) * 4;             // this lane's 4 dims

    // per-lane folded attention weights (4 fixed entries)
    float wl0 = __ldg(&wl[(lq+0)*2 + head]);
    float wl1 = __ldg(&wl[(lq+1)*2 + head]);
    float wl2 = __ldg(&wl[(lq+2)*2 + head]);
    float wl3 = __ldg(&wl[(lq+3)*2 + head]);

    if (tid == 0) qcnt = 0;
    __syncthreads();

    for (long long base = (long long)vb * 256; base < E; base += (long long)nblk * 256) {
        long long i = base + tid;
        bool m = false; int d = 0;
        if (i < E) {
            d = dst[i];
            m = (__ldg(&needb[d >> 5]) >> (d & 31)) & 1u;
        }
        if (m) {
            int p = atomicAdd(&qcnt, 1);
            q[p] = make_int2(src[i], d);
        }
        __syncthreads();
        int n = qcnt;

        for (int e = wid; e < n; e += 8) {
            int2 sd = q[e];
            float4 ev = *(const float4*)&emb[(long long)sd.x * DIMK + lq];
            // inline el = emb[src] . wl[:,head]
            float p = ev.x*wl0 + ev.y*wl1 + ev.z*wl2 + ev.w*wl3;
            #pragma unroll
            for (int o = 8; o; o >>= 1) p += __shfl_xor_sync(0xffffffffu, p, o);
            float e0 = p + er[sd.y*NH + head];
            e0 = e0 > 0.f ? e0 : 0.2f * e0;          // leaky_relu(0.2)
            float ex = __expf(e0);                    // softmax w/o max-shift
            red4(&acc[sd.y*HD + head*DIMK + lq], ex*ev.x, ex*ev.y, ex*ev.z, ex*ev.w);
            if ((l & 15) == 0) atomicAdd(&den[sd.y*NH + head], ex);
        }
        __syncthreads();
        if (tid == 0) qcnt = 0;
        __syncthreads();
    }
}

// ---------------- k_gatfin: (acc/den)@W_head + bias, LN, ELU, head-mean, +emb --
__device__ __forceinline__ float blockSum128(float v, float* sred) {
    #pragma unroll
    for (int o = 16; o; o >>= 1) v += __shfl_xor_sync(0xffffffffu, v, o);
    __syncthreads();
    if ((threadIdx.x & 31) == 0) sred[threadIdx.x >> 5] = v;
    __syncthreads();
    return sred[0] + sred[1] + sred[2] + sred[3];
}

__global__ void __launch_bounds__(128) k_gatfin(
        const int* __restrict__ uidx, const int* __restrict__ sidx,
        const float* __restrict__ uemb, const float* __restrict__ semb,
        const float* __restrict__ uW, const float* __restrict__ sW,
        const float* __restrict__ ubias, const float* __restrict__ ulng, const float* __restrict__ ulnb,
        const float* __restrict__ sbias, const float* __restrict__ slng, const float* __restrict__ slnb) {
    __shared__ float sred[4];
    __shared__ float srow[HD];
    __shared__ float agg[HD];
    int b = blockIdx.x, t = threadIdx.x;
    int u = uidx[b], s = sidx[b];
    int h = t >> 6;                   // head for this output column
    float xu = 0.f, xs = 0.f;

    { // user side
        agg[t] = g_acc_u[u*HD + t] / g_den_u[u*NH + h];
        __syncthreads();
        float v = ubias[t];
        #pragma unroll 4
        for (int k = 0; k < DIMK; k++)
            v += agg[h*DIMK + k] * __ldg(&uW[k*HD + t]);
        float mean = blockSum128(v, sred) * (1.f/HD);
        float d = v - mean;
        float var = blockSum128(d*d, sred) * (1.f/HD);
        float nv = d * rsqrtf(var + 1e-5f) * ulng[t] + ulnb[t];
        nv = nv > 0.f ? nv : expm1f(nv);            // ELU
        __syncthreads();
        srow[t] = nv;
        __syncthreads();
        if (t < DIMK) xu = 0.5f*(srow[t] + srow[t+DIMK]) + uemb[u*DIMK + t];
        __syncthreads();
    }
    { // service side
        agg[t] = g_acc_s[s*HD + t] / g_den_s[s*NH + h];
        __syncthreads();
        float v = sbias[t];
        #pragma unroll 4
        for (int k = 0; k < DIMK; k++)
            v += agg[h*DIMK + k] * __ldg(&sW[k*HD + t]);
        float mean = blockSum128(v, sred) * (1.f/HD);
        float d = v - mean;
        float var = blockSum128(d*d, sred) * (1.f/HD);
        float nv = d * rsqrtf(var + 1e-5f) * slng[t] + slnb[t];
        nv = nv > 0.f ? nv : expm1f(nv);
        __syncthreads();
        srow[t] = nv;
        __syncthreads();
        if (t < DIMK) xs = 0.5f*(srow[t] + srow[t+DIMK]) + semb[s*DIMK + t];
    }
    if (t < DIMK) {
        g_x[b*HD + t]        = xu;
        g_x[b*HD + DIMK + t] = xs;
    }
}

// ---------------- k_mlp: fused 128->128->128->1 with LN/relu, sigmoid ----------
__global__ void __launch_bounds__(256) k_mlp(
        const float* __restrict__ W1, const float* __restrict__ b1,
        const float* __restrict__ g1, const float* __restrict__ bb1,
        const float* __restrict__ W2, const float* __restrict__ b2,
        const float* __restrict__ g2, const float* __restrict__ bb2,
        const float* __restrict__ W3, const float* __restrict__ b3,
        float* __restrict__ out) {
    __shared__ float xs[32][HD];       // 16 KB
    __shared__ float Wch[32*HD];       // 16 KB
    int tid = threadIdx.x;
    int rbase = blockIdx.x * 32;
    int w = tid >> 5, l = tid & 31;
    int r0 = w * 4, c0 = l * 4;

    for (int i = tid; i < 32*HD; i += 256) ((float*)xs)[i] = g_x[rbase*HD + i];

    const float* Wp[2]  = {W1, W2};
    const float* bp[2]  = {b1, b2};
    const float* gp[2]  = {g1, g2};
    const float* bbp[2] = {bb1, bb2};
    float val[4][4];

    for (int layer = 0; layer < 2; layer++) {
        float acc[4][4] = {};
        for (int kc = 0; kc < 4; kc++) {
            __syncthreads();
            for (int i = tid; i < 32*HD; i += 256) Wch[i] = Wp[layer][kc*32*HD + i];
            __syncthreads();
            #pragma unroll
            for (int k4 = 0; k4 < 32; k4 += 4) {
                float4 A0 = *(const float4*)&xs[r0+0][kc*32 + k4];
                float4 A1 = *(const float4*)&xs[r0+1][kc*32 + k4];
                float4 A2 = *(const float4*)&xs[r0+2][kc*32 + k4];
                float4 A3 = *(const float4*)&xs[r0+3][kc*32 + k4];
                #pragma unroll
                for (int kk = 0; kk < 4; kk++) {
                    float4 wv = *(const float4*)&Wch[(k4+kk)*HD + c0];
                    float e0 = FCMP(A0,kk), e1 = FCMP(A1,kk), e2 = FCMP(A2,kk), e3 = FCMP(A3,kk);
                    acc[0][0] += e0*wv.x; acc[0][1] += e0*wv.y; acc[0][2] += e0*wv.z; acc[0][3] += e0*wv.w;
                    acc[1][0] += e1*wv.x; acc[1][1] += e1*wv.y; acc[1][2] += e1*wv.z; acc[1][3] += e1*wv.w;
                    acc[2][0] += e2*wv.x; acc[2][1] += e2*wv.y; acc[2][2] += e2*wv.z; acc[2][3] += e2*wv.w;
                    acc[3][0] += e3*wv.x; acc[3][1] += e3*wv.y; acc[3][2] += e3*wv.z; acc[3][3] += e3*wv.w;
                }
            }
        }
        __syncthreads();

        float4 bv  = *(const float4*)&bp[layer][c0];
        float4 gv  = *(const float4*)&gp[layer][c0];
        float4 bbv = *(const float4*)&bbp[layer][c0];
        #pragma unroll
        for (int i = 0; i < 4; i++) {
            float a0 = acc[i][0] + bv.x, a1 = acc[i][1] + bv.y;
            float a2 = acc[i][2] + bv.z, a3 = acc[i][3] + bv.w;
            float sum = a0 + a1 + a2 + a3;
            #pragma unroll
            for (int o = 16; o; o >>= 1) sum += __shfl_xor_sync(0xffffffffu, sum, o);
            float mean = sum * (1.f/HD);
            float d0 = a0-mean, d1 = a1-mean, d2 = a2-mean, d3 = a3-mean;
            float sq = d0*d0 + d1*d1 + d2*d2 + d3*d3;
            #pragma unroll
            for (int o = 16; o; o >>= 1) sq += __shfl_xor_sync(0xffffffffu, sq, o);
            float rstd = rsqrtf(sq * (1.f/HD) + 1e-5f);
            float v0 = fmaxf(d0*rstd*gv.x + bbv.x, 0.f);
            float v1 = fmaxf(d1*rstd*gv.y + bbv.y, 0.f);
            float v2 = fmaxf(d2*rstd*gv.z + bbv.z, 0.f);
            float v3 = fmaxf(d3*rstd*gv.w + bbv.w, 0.f);
            xs[r0+i][c0+0] = v0; xs[r0+i][c0+1] = v1;
            xs[r0+i][c0+2] = v2; xs[r0+i][c0+3] = v3;
            val[i][0] = v0; val[i][1] = v1; val[i][2] = v2; val[i][3] = v3;
        }
    }

    float4 w3 = *(const float4*)&W3[c0];
    float bias3 = b3[0];
    #pragma unroll
    for (int i = 0; i < 4; i++) {
        float p = val[i][0]*w3.x + val[i][1]*w3.y + val[i][2]*w3.z + val[i][3]*w3.w;
        #pragma unroll
        for (int o = 16; o; o >>= 1) p += __shfl_xor_sync(0xffffffffu, p, o);
        if (l == 0) out[rbase + r0 + i] = 1.f / (1.f + __expf(-(p + bias3)));
    }
}

// ---------------- launch --------------------------------------------------------
extern "C" void kernel_launch(void* const* d_in, const int* in_sizes, int n_in,
                              void* d_out, int out_size) {
    const int*   uidx  = (const int*)  d_in[0];
    const int*   sidx  = (const int*)  d_in[1];
    const int*   usrc  = (const int*)  d_in[2];
    const int*   udst  = (const int*)  d_in[3];
    const int*   ssrc  = (const int*)  d_in[4];
    const int*   sdst  = (const int*)  d_in[5];
    const float* uemb  = (const float*)d_in[6];
    const float* semb  = (const float*)d_in[7];
    const float* uW    = (const float*)d_in[8];
    const float* ual   = (const float*)d_in[9];
    const float* uar   = (const float*)d_in[10];
    const float* ubias = (const float*)d_in[11];
    const float* ulng  = (const float*)d_in[12];
    const float* ulnb  = (const float*)d_in[13];
    const float* sW    = (const float*)d_in[14];
    const float* sal   = (const float*)d_in[15];
    const float* sar   = (const float*)d_in[16];
    const float* sbias = (const float*)d_in[17];
    const float* slng  = (const float*)d_in[18];
    const float* slnb  = (const float*)d_in[19];
    const float* W1    = (const float*)d_in[20];
    const float* b1    = (const float*)d_in[21];
    const float* g1    = (const float*)d_in[22];
    const float* bb1   = (const float*)d_in[23];
    const float* W2    = (const float*)d_in[24];
    const float* b2    = (const float*)d_in[25];
    const float* g2    = (const float*)d_in[26];
    const float* bb2   = (const float*)d_in[27];
    const float* W3    = (const float*)d_in[28];
    const float* b3    = (const float*)d_in[29];
    float* out = (float*)d_out;

    int B  = in_sizes[0];
    int Eu = in_sizes[2];
    int Es = in_sizes[4];

    k_zero<<<32, 256>>>();
    k_wvec<<<1, 256>>>(uW, ual, uar, sW, sal, sar);
    k_mark<<<B, 128>>>(uidx, sidx, uemb, semb);
    {
        // split grid roughly proportional to edge counts (Es ~= 2*Eu)
        int gu = 592, gs = 1184;
        k_edge_all<<<gu + gs, 256>>>(usrc, udst, Eu, ssrc, sdst, Es,
                                     uemb, semb, gu);
    }
    k_gatfin<<<B, 128>>>(uidx, sidx, uemb, semb, uW, sW,
                         ubias, ulng, ulnb, sbias, slng, slnb);
    k_mlp<<<B/32, 256>>>(W1, b1, g1, bb1, W2, b2, g2, bb2, W3, b3, out);
}

// round 7
// speedup vs baseline: 2.8109x; 1.2726x over previous
#include <cuda_runtime.h>
#include <math.h>

#define NU 100000
#define NS 200000
#define DIMK 64
#define NH 2
#define HD 128          // NH * DIMK
#define BMAX 16384
#define NUW ((NU+31)/32)
#define NSW ((NS+31)/32)

// ---------------- scratch (static device globals) -------------------------------
__device__ float g_acc_u[NU*HD];     // per-dst: sum ex * emb[src]  (head-major)
__device__ float g_acc_s[NS*HD];
__device__ float g_den_u[NU*NH];
__device__ float g_den_s[NS*NH];
__device__ float g_er_u[NU*NH];      // er for needed dsts, [node*2+h]
__device__ float g_er_s[NS*NH];
__device__ float g_wl_u[DIMK*NH];    // W @ a_l folded vectors, [k*2+h]
__device__ float g_wr_u[DIMK*NH];
__device__ float g_wl_s[DIMK*NH];
__device__ float g_wr_s[DIMK*NH];
__device__ unsigned g_needb_u[NUW];
__device__ unsigned g_needb_s[NSW];
__device__ float g_x[BMAX*HD];

// ---------------- helpers ------------------------------------------------------
__device__ __forceinline__ void red4(float* p, float a, float b, float c, float d) {
    asm volatile("{ .reg .u64 q; cvta.to.global.u64 q, %0;"
                 "  red.global.add.v4.f32 [q], {%1, %2, %3, %4}; }"
                 :: "l"(p), "f"(a), "f"(b), "f"(c), "f"(d) : "memory");
}

#define FCMP(v,kk) ((kk)==0?(v).x:((kk)==1?(v).y:((kk)==2?(v).z:(v).w)))

// ---------------- k_init: reset need bitmasks (blocks 0..N-2) + wvec (last) ----
// wl[k,h] = sum_d W[k, h*64+d] * al[h,d]   (and same for wr/ar)
__global__ void __launch_bounds__(256) k_init(const float* __restrict__ uW,
                                              const float* __restrict__ ual,
                                              const float* __restrict__ uar,
                                              const float* __restrict__ sW,
                                              const float* __restrict__ sal,
                                              const float* __restrict__ sar) {
    if (blockIdx.x == gridDim.x - 1) {
        int tid = threadIdx.x;            // 0..255
        int user = tid < 128;
        int t = tid & 127;
        int k = t >> 1, h = t & 1;
        const float* W  = user ? uW  : sW;
        const float* al = user ? ual : sal;
        const float* ar = user ? uar : sar;
        float accl = 0.f, accr = 0.f;
        #pragma unroll 8
        for (int d = 0; d < DIMK; d++) {
            float w = W[k*HD + h*DIMK + d];
            accl += w * al[h*DIMK + d];
            accr += w * ar[h*DIMK + d];
        }
        if (user) { g_wl_u[k*2+h] = accl; g_wr_u[k*2+h] = accr; }
        else      { g_wl_s[k*2+h] = accl; g_wr_s[k*2+h] = accr; }
        return;
    }
    int i = blockIdx.x*blockDim.x + threadIdx.x;
    int st = (gridDim.x-1)*blockDim.x;
    for (int j = i; j < NUW; j += st) g_needb_u[j] = 0u;
    for (int j = i; j < NSW; j += st) g_needb_s[j] = 0u;
}

// ---------------- k_mark: mark bits, zero acc/den, compute er for dsts ---------
__global__ void __launch_bounds__(128) k_mark(const int* __restrict__ uidx,
                                              const int* __restrict__ sidx,
                                              const float* __restrict__ uemb,
                                              const float* __restrict__ semb) {
    int b = blockIdx.x, t = threadIdx.x;
    int u = uidx[b], s = sidx[b];
    g_acc_u[u*HD + t] = 0.f;
    g_acc_s[s*HD + t] = 0.f;
    if (t < NH) { g_den_u[u*NH + t] = 0.f; g_den_s[s*NH + t] = 0.f; }
    if (t == 0) {
        atomicOr(&g_needb_u[u >> 5], 1u << (u & 31));
        atomicOr(&g_needb_s[s >> 5], 1u << (s & 31));
    }
    // er[d,h] = emb[d] . wr[:,h]; one warp per (side, head)
    {
        int wid = t >> 5, l = t & 31;
        int user = wid < 2, head = wid & 1;
        int node = user ? u : s;
        const float* emb = user ? uemb : semb;
        const float* wr  = user ? g_wr_u : g_wr_s;
        float* er        = user ? g_er_u : g_er_s;
        int k2 = l * 2;
        float2 ev = *(const float2*)&emb[(long long)node*DIMK + k2];
        float p = ev.x * __ldg(&wr[k2*2 + head]) + ev.y * __ldg(&wr[(k2+1)*2 + head]);
        #pragma unroll
        for (int o = 16; o; o >>= 1) p += __shfl_xor_sync(0xffffffffu, p, o);
        if (l == 0) er[node*NH + head] = p;
    }
}

// ---------------- k_edge_all: ballot-compact + 2-edge-ILP drain ----------------
// Each warp streams 32 coalesced dsts, ballots matches, processes matched
// edges two at a time (warp-wide: 16 lanes per head, 4 dims per lane).
__global__ void __launch_bounds__(256) k_edge_all(const int* __restrict__ usrc,
                                                  const int* __restrict__ udst, int Eu,
                                                  const int* __restrict__ ssrc,
                                                  const int* __restrict__ sdst, int Es,
                                                  const float* __restrict__ uemb,
                                                  const float* __restrict__ semb,
                                                  int splitBlk) {
    int user = (blockIdx.x < splitBlk);
    const int* __restrict__ src = user ? usrc : ssrc;
    const int* __restrict__ dst = user ? udst : sdst;
    int E = user ? Eu : Es;
    const unsigned* __restrict__ needb = user ? g_needb_u : g_needb_s;
    const float* __restrict__ emb = user ? uemb : semb;
    const float* __restrict__ wl  = user ? g_wl_u : g_wl_s;
    const float* __restrict__ er  = user ? g_er_u : g_er_s;
    float* acc = user ? g_acc_u : g_acc_s;
    float* den = user ? g_den_u : g_den_s;
    int vb   = user ? blockIdx.x : blockIdx.x - splitBlk;
    int nblk = user ? splitBlk : gridDim.x - splitBlk;

    int tid = threadIdx.x;
    int wid = tid >> 5, l = tid & 31;
    int head = l >> 4;
    int lq = (l & 15) * 4;             // this lane's 4 dims

    float wl0 = __ldg(&wl[(lq+0)*2 + head]);
    float wl1 = __ldg(&wl[(lq+1)*2 + head]);
    float wl2 = __ldg(&wl[(lq+2)*2 + head]);
    float wl3 = __ldg(&wl[(lq+3)*2 + head]);

    long long gwarp = (long long)vb*8 + wid;
    long long nwarp = (long long)nblk*8;

    for (long long base = gwarp*32; base < E; base += nwarp*32) {
        long long i = base + l;
        int d = 0, s = 0; bool m = false;
        if (i < E) {
            d = dst[i];
            m = (__ldg(&needb[d >> 5]) >> (d & 31)) & 1u;
        }
        unsigned bal = __ballot_sync(0xffffffffu, m);
        if (m) s = src[i];

        while (bal) {
            int b0 = __ffs(bal) - 1; bal &= bal - 1;
            bool has1 = (bal != 0);
            int b1 = has1 ? (__ffs(bal) - 1) : b0;
            if (has1) bal &= bal - 1;

            int s0 = __shfl_sync(0xffffffffu, s, b0);
            int d0 = __shfl_sync(0xffffffffu, d, b0);
            int s1 = __shfl_sync(0xffffffffu, s, b1);
            int d1 = __shfl_sync(0xffffffffu, d, b1);

            // issue both gathers before reducing either
            float4 e0 = *(const float4*)&emb[(long long)s0 * DIMK + lq];
            float4 e1 = *(const float4*)&emb[(long long)s1 * DIMK + lq];

            float p0 = e0.x*wl0 + e0.y*wl1 + e0.z*wl2 + e0.w*wl3;
            float p1 = e1.x*wl0 + e1.y*wl1 + e1.z*wl2 + e1.w*wl3;
            #pragma unroll
            for (int o = 8; o; o >>= 1) {
                p0 += __shfl_xor_sync(0xffffffffu, p0, o);
                p1 += __shfl_xor_sync(0xffffffffu, p1, o);
            }
            float a0 = p0 + er[d0*NH + head];
            float a1 = p1 + er[d1*NH + head];
            a0 = a0 > 0.f ? a0 : 0.2f * a0;          // leaky_relu(0.2)
            a1 = a1 > 0.f ? a1 : 0.2f * a1;
            float x0 = __expf(a0);
            float x1 = __expf(a1);

            red4(&acc[d0*HD + head*DIMK + lq], x0*e0.x, x0*e0.y, x0*e0.z, x0*e0.w);
            if ((l & 15) == 0) atomicAdd(&den[d0*NH + head], x0);
            if (has1) {
                red4(&acc[d1*HD + head*DIMK + lq], x1*e1.x, x1*e1.y, x1*e1.z, x1*e1.w);
                if ((l & 15) == 0) atomicAdd(&den[d1*NH + head], x1);
            }
        }
    }
}

// ---------------- k_gatfin: warp-per-row, zero block barriers ------------------
// (acc/den)@W_head + bias, LN over 128, ELU, head-mean, +emb -> g_x
__global__ void __launch_bounds__(256) k_gatfin(
        const int* __restrict__ uidx, const int* __restrict__ sidx,
        const float* __restrict__ uemb, const float* __restrict__ semb,
        const float* __restrict__ uW, const float* __restrict__ sW,
        const float* __restrict__ ubias, const float* __restrict__ ulng, const float* __restrict__ ulnb,
        const float* __restrict__ sbias, const float* __restrict__ slng, const float* __restrict__ slnb) {
    __shared__ float sAgg[8][NH][68];          // bank-padded per-warp agg strip
    int tid = threadIdx.x;
    int wid = tid >> 5, l = tid & 31;
    int r = blockIdx.x * 8 + wid;
    int h = l >> 4;                            // this lane's head
    int c = l * 4;                             // this lane's 4 columns (0..124)
    int kk = (l & 15) * 4;                     // position within head

    int u = uidx[r], s = sidx[r];
    float ox[2][4];                            // [side][j] head-mean outputs (l<16)

    #pragma unroll
    for (int side = 0; side < 2; side++) {
        const float* accp = side ? g_acc_s : g_acc_u;
        const float* denp = side ? g_den_s : g_den_u;
        const float* W    = side ? sW : uW;
        const float* bias = side ? sbias : ubias;
        const float* lng  = side ? slng : ulng;
        const float* lnb  = side ? slnb : ulnb;
        const float* emb  = side ? semb : uemb;
        int node = side ? s : u;

        float dn = denp[node*NH + h];
        float4 a4 = *(const float4*)&accp[node*HD + c];
        float inv = 1.f / dn;
        sAgg[wid][h][kk+0] = a4.x * inv;
        sAgg[wid][h][kk+1] = a4.y * inv;
        sAgg[wid][h][kk+2] = a4.z * inv;
        sAgg[wid][h][kk+3] = a4.w * inv;
        __syncwarp();

        float4 bv = *(const float4*)&bias[c];
        float v0 = bv.x, v1 = bv.y, v2 = bv.z, v3 = bv.w;
        #pragma unroll 8
        for (int k = 0; k < DIMK; k++) {
            float ag = sAgg[wid][h][k];
            float4 wv = *(const float4*)&W[k*HD + c];
            v0 += ag*wv.x; v1 += ag*wv.y; v2 += ag*wv.z; v3 += ag*wv.w;
        }

        float sum = v0+v1+v2+v3;
        #pragma unroll
        for (int o = 16; o; o >>= 1) sum += __shfl_xor_sync(0xffffffffu, sum, o);
        float mean = sum * (1.f/HD);
        float d0 = v0-mean, d1 = v1-mean, d2 = v2-mean, d3 = v3-mean;
        float sq = d0*d0 + d1*d1 + d2*d2 + d3*d3;
        #pragma unroll
        for (int o = 16; o; o >>= 1) sq += __shfl_xor_sync(0xffffffffu, sq, o);
        float rstd = rsqrtf(sq * (1.f/HD) + 1e-5f);

        float4 gv = *(const float4*)&lng[c];
        float4 bb = *(const float4*)&lnb[c];
        float n0 = d0*rstd*gv.x + bb.x;
        float n1 = d1*rstd*gv.y + bb.y;
        float n2 = d2*rstd*gv.z + bb.z;
        float n3 = d3*rstd*gv.w + bb.w;
        n0 = n0 > 0.f ? n0 : expm1f(n0);       // ELU
        n1 = n1 > 0.f ? n1 : expm1f(n1);
        n2 = n2 > 0.f ? n2 : expm1f(n2);
        n3 = n3 > 0.f ? n3 : expm1f(n3);

        // head-mean: lane l (<16) pairs with lane l+16
        float m0 = __shfl_xor_sync(0xffffffffu, n0, 16);
        float m1 = __shfl_xor_sync(0xffffffffu, n1, 16);
        float m2 = __shfl_xor_sync(0xffffffffu, n2, 16);
        float m3 = __shfl_xor_sync(0xffffffffu, n3, 16);
        if (l < 16) {
            float4 e4 = *(const float4*)&emb[(long long)node*DIMK + c];
            ox[side][0] = 0.5f*(n0+m0) + e4.x;
            ox[side][1] = 0.5f*(n1+m1) + e4.y;
            ox[side][2] = 0.5f*(n2+m2) + e4.z;
            ox[side][3] = 0.5f*(n3+m3) + e4.w;
        }
        __syncwarp();                          // sAgg reuse barrier
    }

    if (l < 16) {
        *(float4*)&g_x[r*HD + c]        = make_float4(ox[0][0], ox[0][1], ox[0][2], ox[0][3]);
        *(float4*)&g_x[r*HD + DIMK + c] = make_float4(ox[1][0], ox[1][1], ox[1][2], ox[1][3]);
    }
}

// ---------------- k_mlp: fused 128->128->128->1 with LN/relu, sigmoid ----------
__global__ void __launch_bounds__(256) k_mlp(
        const float* __restrict__ W1, const float* __restrict__ b1,
        const float* __restrict__ g1, const float* __restrict__ bb1,
        const float* __restrict__ W2, const float* __restrict__ b2,
        const float* __restrict__ g2, const float* __restrict__ bb2,
        const float* __restrict__ W3, const float* __restrict__ b3,
        float* __restrict__ out) {
    __shared__ float xs[32][HD];       // 16 KB
    __shared__ float Wch[32*HD];       // 16 KB
    int tid = threadIdx.x;
    int rbase = blockIdx.x * 32;
    int w = tid >> 5, l = tid & 31;
    int r0 = w * 4, c0 = l * 4;

    for (int i = tid; i < 32*HD; i += 256) ((float*)xs)[i] = g_x[rbase*HD + i];

    const float* Wp[2]  = {W1, W2};
    const float* bp[2]  = {b1, b2};
    const float* gp[2]  = {g1, g2};
    const float* bbp[2] = {bb1, bb2};
    float val[4][4];

    for (int layer = 0; layer < 2; layer++) {
        float acc[4][4] = {};
        for (int kc = 0; kc < 4; kc++) {
            __syncthreads();
            for (int i = tid; i < 32*HD; i += 256) Wch[i] = Wp[layer][kc*32*HD + i];
            __syncthreads();
            #pragma unroll
            for (int k4 = 0; k4 < 32; k4 += 4) {
                float4 A0 = *(const float4*)&xs[r0+0][kc*32 + k4];
                float4 A1 = *(const float4*)&xs[r0+1][kc*32 + k4];
                float4 A2 = *(const float4*)&xs[r0+2][kc*32 + k4];
                float4 A3 = *(const float4*)&xs[r0+3][kc*32 + k4];
                #pragma unroll
                for (int kk = 0; kk < 4; kk++) {
                    float4 wv = *(const float4*)&Wch[(k4+kk)*HD + c0];
                    float e0 = FCMP(A0,kk), e1 = FCMP(A1,kk), e2 = FCMP(A2,kk), e3 = FCMP(A3,kk);
                    acc[0][0] += e0*wv.x; acc[0][1] += e0*wv.y; acc[0][2] += e0*wv.z; acc[0][3] += e0*wv.w;
                    acc[1][0] += e1*wv.x; acc[1][1] += e1*wv.y; acc[1][2] += e1*wv.z; acc[1][3] += e1*wv.w;
                    acc[2][0] += e2*wv.x; acc[2][1] += e2*wv.y; acc[2][2] += e2*wv.z; acc[2][3] += e2*wv.w;
                    acc[3][0] += e3*wv.x; acc[3][1] += e3*wv.y; acc[3][2] += e3*wv.z; acc[3][3] += e3*wv.w;
                }
            }
        }
        __syncthreads();

        float4 bv  = *(const float4*)&bp[layer][c0];
        float4 gv  = *(const float4*)&gp[layer][c0];
        float4 bbv = *(const float4*)&bbp[layer][c0];
        #pragma unroll
        for (int i = 0; i < 4; i++) {
            float a0 = acc[i][0] + bv.x, a1 = acc[i][1] + bv.y;
            float a2 = acc[i][2] + bv.z, a3 = acc[i][3] + bv.w;
            float sum = a0 + a1 + a2 + a3;
            #pragma unroll
            for (int o = 16; o; o >>= 1) sum += __shfl_xor_sync(0xffffffffu, sum, o);
            float mean = sum * (1.f/HD);
            float d0 = a0-mean, d1 = a1-mean, d2 = a2-mean, d3 = a3-mean;
            float sq = d0*d0 + d1*d1 + d2*d2 + d3*d3;
            #pragma unroll
            for (int o = 16; o; o >>= 1) sq += __shfl_xor_sync(0xffffffffu, sq, o);
            float rstd = rsqrtf(sq * (1.f/HD) + 1e-5f);
            float v0 = fmaxf(d0*rstd*gv.x + bbv.x, 0.f);
            float v1 = fmaxf(d1*rstd*gv.y + bbv.y, 0.f);
            float v2 = fmaxf(d2*rstd*gv.z + bbv.z, 0.f);
            float v3 = fmaxf(d3*rstd*gv.w + bbv.w, 0.f);
            xs[r0+i][c0+0] = v0; xs[r0+i][c0+1] = v1;
            xs[r0+i][c0+2] = v2; xs[r0+i][c0+3] = v3;
            val[i][0] = v0; val[i][1] = v1; val[i][2] = v2; val[i][3] = v3;
        }
    }

    float4 w3 = *(const float4*)&W3[c0];
    float bias3 = b3[0];
    #pragma unroll
    for (int i = 0; i < 4; i++) {
        float p = val[i][0]*w3.x + val[i][1]*w3.y + val[i][2]*w3.z + val[i][3]*w3.w;
        #pragma unroll
        for (int o = 16; o; o >>= 1) p += __shfl_xor_sync(0xffffffffu, p, o);
        if (l == 0) out[rbase + r0 + i] = 1.f / (1.f + __expf(-(p + bias3)));
    }
}

// ---------------- launch --------------------------------------------------------
extern "C" void kernel_launch(void* const* d_in, const int* in_sizes, int n_in,
                              void* d_out, int out_size) {
    const int*   uidx  = (const int*)  d_in[0];
    const int*   sidx  = (const int*)  d_in[1];
    const int*   usrc  = (const int*)  d_in[2];
    const int*   udst  = (const int*)  d_in[3];
    const int*   ssrc  = (const int*)  d_in[4];
    const int*   sdst  = (const int*)  d_in[5];
    const float* uemb  = (const float*)d_in[6];
    const float* semb  = (const float*)d_in[7];
    const float* uW    = (const float*)d_in[8];
    const float* ual   = (const float*)d_in[9];
    const float* uar   = (const float*)d_in[10];
    const float* ubias = (const float*)d_in[11];
    const float* ulng  = (const float*)d_in[12];
    const float* ulnb  = (const float*)d_in[13];
    const float* sW    = (const float*)d_in[14];
    const float* sal   = (const float*)d_in[15];
    const float* sar   = (const float*)d_in[16];
    const float* sbias = (const float*)d_in[17];
    const float* slng  = (const float*)d_in[18];
    const float* slnb  = (const float*)d_in[19];
    const float* W1    = (const float*)d_in[20];
    const float* b1    = (const float*)d_in[21];
    const float* g1    = (const float*)d_in[22];
    const float* bb1   = (const float*)d_in[23];
    const float* W2    = (const float*)d_in[24];
    const float* b2    = (const float*)d_in[25];
    const float* g2    = (const float*)d_in[26];
    const float* bb2   = (const float*)d_in[27];
    const float* W3    = (const float*)d_in[28];
    const float* b3    = (const float*)d_in[29];
    float* out = (float*)d_out;

    int B  = in_sizes[0];
    int Eu = in_sizes[2];
    int Es = in_sizes[4];

    k_init<<<33, 256>>>(uW, ual, uar, sW, sal, sar);
    k_mark<<<B, 128>>>(uidx, sidx, uemb, semb);
    {
        int gu = 592, gs = 1184;   // split ~ Eu : Es
        k_edge_all<<<gu + gs, 256>>>(usrc, udst, Eu, ssrc, sdst, Es,
                                     uemb, semb, gu);
    }
    k_gatfin<<<B/8, 256>>>(uidx, sidx, uemb, semb, uW, sW,
                           ubias, ulng, ulnb, sbias, slng, slnb);
    k_mlp<<<B/32, 256>>>(W1, b1, g1, bb1, W2, b2, g2, bb2, W3, b3, out);
}

// round 9
// speedup vs baseline: 3.0582x; 1.0879x over previous
#include <cuda_runtime.h>
#include <math.h>

#define NU 100000
#define NS 200000
#define DIMK 64
#define NH 2
#define HD 128          // NH * DIMK
#define BMAX 16384
#define NUW ((NU+31)/32)
#define NSW ((NS+31)/32)

// ---------------- scratch (static device globals) -------------------------------
__device__ float g_acc_u[NU*HD];     // per-dst: sum ex * emb[src]  (head-major)
__device__ float g_acc_s[NS*HD];
__device__ float g_den_u[NU*NH];
__device__ float g_den_s[NS*NH];
__device__ float g_er_u[NU*NH];      // er for needed dsts, [node*2+h]
__device__ float g_er_s[NS*NH];
__device__ float g_wl_u[DIMK*NH];    // W @ a_l folded vectors, [k*2+h]
__device__ float g_wr_u[DIMK*NH];
__device__ float g_wl_s[DIMK*NH];
__device__ float g_wr_s[DIMK*NH];
__device__ unsigned g_needb_u[NUW];
__device__ unsigned g_needb_s[NSW];

// ---------------- helpers ------------------------------------------------------
__device__ __forceinline__ void red4(float* p, float a, float b, float c, float d) {
    asm volatile("{ .reg .u64 q; cvta.to.global.u64 q, %0;"
                 "  red.global.add.v4.f32 [q], {%1, %2, %3, %4}; }"
                 :: "l"(p), "f"(a), "f"(b), "f"(c), "f"(d) : "memory");
}

#define FCMP(v,kk) ((kk)==0?(v).x:((kk)==1?(v).y:((kk)==2?(v).z:(v).w)))

// ---------------- k_init: reset need bitmasks (blocks 0..N-2) + wvec (last) ----
__global__ void __launch_bounds__(256) k_init(const float* __restrict__ uW,
                                              const float* __restrict__ ual,
                                              const float* __restrict__ uar,
                                              const float* __restrict__ sW,
                                              const float* __restrict__ sal,
                                              const float* __restrict__ sar) {
    if (blockIdx.x == gridDim.x - 1) {
        int tid = threadIdx.x;            // 0..255
        int user = tid < 128;
        int t = tid & 127;
        int k = t >> 1, h = t & 1;
        const float* W  = user ? uW  : sW;
        const float* al = user ? ual : sal;
        const float* ar = user ? uar : sar;
        float accl = 0.f, accr = 0.f;
        #pragma unroll 8
        for (int d = 0; d < DIMK; d++) {
            float w = W[k*HD + h*DIMK + d];
            accl += w * al[h*DIMK + d];
            accr += w * ar[h*DIMK + d];
        }
        if (user) { g_wl_u[k*2+h] = accl; g_wr_u[k*2+h] = accr; }
        else      { g_wl_s[k*2+h] = accl; g_wr_s[k*2+h] = accr; }
        return;
    }
    int i = blockIdx.x*blockDim.x + threadIdx.x;
    int st = (gridDim.x-1)*blockDim.x;
    for (int j = i; j < NUW; j += st) g_needb_u[j] = 0u;
    for (int j = i; j < NSW; j += st) g_needb_s[j] = 0u;
}

// ---------------- k_mark: mark bits, zero acc/den, compute er for dsts ---------
__global__ void __launch_bounds__(128) k_mark(const int* __restrict__ uidx,
                                              const int* __restrict__ sidx,
                                              const float* __restrict__ uemb,
                                              const float* __restrict__ semb) {
    int b = blockIdx.x, t = threadIdx.x;
    int u = uidx[b], s = sidx[b];
    g_acc_u[u*HD + t] = 0.f;
    g_acc_s[s*HD + t] = 0.f;
    if (t < NH) { g_den_u[u*NH + t] = 0.f; g_den_s[s*NH + t] = 0.f; }
    if (t == 0) {
        atomicOr(&g_needb_u[u >> 5], 1u << (u & 31));
        atomicOr(&g_needb_s[s >> 5], 1u << (s & 31));
    }
    // er[d,h] = emb[d] . wr[:,h]; one warp per (side, head)
    {
        int wid = t >> 5, l = t & 31;
        int user = wid < 2, head = wid & 1;
        int node = user ? u : s;
        const float* emb = user ? uemb : semb;
        const float* wr  = user ? g_wr_u : g_wr_s;
        float* er        = user ? g_er_u : g_er_s;
        int k2 = l * 2;
        float2 ev = *(const float2*)&emb[(long long)node*DIMK + k2];
        float p = ev.x * __ldg(&wr[k2*2 + head]) + ev.y * __ldg(&wr[(k2+1)*2 + head]);
        #pragma unroll
        for (int o = 16; o; o >>= 1) p += __shfl_xor_sync(0xffffffffu, p, o);
        if (l == 0) er[node*NH + head] = p;
    }
}

// ---------------- k_edge_all: ballot-compact + 2-edge-ILP drain ----------------
__global__ void __launch_bounds__(256) k_edge_all(const int* __restrict__ usrc,
                                                  const int* __restrict__ udst, int Eu,
                                                  const int* __restrict__ ssrc,
                                                  const int* __restrict__ sdst, int Es,
                                                  const float* __restrict__ uemb,
                                                  const float* __restrict__ semb,
                                                  int splitBlk) {
    int user = (blockIdx.x < splitBlk);
    const int* __restrict__ src = user ? usrc : ssrc;
    const int* __restrict__ dst = user ? udst : sdst;
    int E = user ? Eu : Es;
    const unsigned* __restrict__ needb = user ? g_needb_u : g_needb_s;
    const float* __restrict__ emb = user ? uemb : semb;
    const float* __restrict__ wl  = user ? g_wl_u : g_wl_s;
    const float* __restrict__ er  = user ? g_er_u : g_er_s;
    float* acc = user ? g_acc_u : g_acc_s;
    float* den = user ? g_den_u : g_den_s;
    int vb   = user ? blockIdx.x : blockIdx.x - splitBlk;
    int nblk = user ? splitBlk : gridDim.x - splitBlk;

    int tid = threadIdx.x;
    int wid = tid >> 5, l = tid & 31;
    int head = l >> 4;
    int lq = (l & 15) * 4;

    float wl0 = __ldg(&wl[(lq+0)*2 + head]);
    float wl1 = __ldg(&wl[(lq+1)*2 + head]);
    float wl2 = __ldg(&wl[(lq+2)*2 + head]);
    float wl3 = __ldg(&wl[(lq+3)*2 + head]);

    long long gwarp = (long long)vb*8 + wid;
    long long nwarp = (long long)nblk*8;

    for (long long base = gwarp*32; base < E; base += nwarp*32) {
        long long i = base + l;
        int d = 0, s = 0; bool m = false;
        if (i < E) {
            d = dst[i];
            m = (__ldg(&needb[d >> 5]) >> (d & 31)) & 1u;
        }
        unsigned bal = __ballot_sync(0xffffffffu, m);
        if (m) s = src[i];

        while (bal) {
            int b0 = __ffs(bal) - 1; bal &= bal - 1;
            bool has1 = (bal != 0);
            int b1 = has1 ? (__ffs(bal) - 1) : b0;
            if (has1) bal &= bal - 1;

            int s0 = __shfl_sync(0xffffffffu, s, b0);
            int d0 = __shfl_sync(0xffffffffu, d, b0);
            int s1 = __shfl_sync(0xffffffffu, s, b1);
            int d1 = __shfl_sync(0xffffffffu, d, b1);

            float4 e0 = *(const float4*)&emb[(long long)s0 * DIMK + lq];
            float4 e1 = *(const float4*)&emb[(long long)s1 * DIMK + lq];

            float p0 = e0.x*wl0 + e0.y*wl1 + e0.z*wl2 + e0.w*wl3;
            float p1 = e1.x*wl0 + e1.y*wl1 + e1.z*wl2 + e1.w*wl3;
            #pragma unroll
            for (int o = 8; o; o >>= 1) {
                p0 += __shfl_xor_sync(0xffffffffu, p0, o);
                p1 += __shfl_xor_sync(0xffffffffu, p1, o);
            }
            float a0 = p0 + er[d0*NH + head];
            float a1 = p1 + er[d1*NH + head];
            a0 = a0 > 0.f ? a0 : 0.2f * a0;
            a1 = a1 > 0.f ? a1 : 0.2f * a1;
            float x0 = __expf(a0);
            float x1 = __expf(a1);

            red4(&acc[d0*HD + head*DIMK + lq], x0*e0.x, x0*e0.y, x0*e0.z, x0*e0.w);
            if ((l & 15) == 0) atomicAdd(&den[d0*NH + head], x0);
            if (has1) {
                red4(&acc[d1*HD + head*DIMK + lq], x1*e1.x, x1*e1.y, x1*e1.z, x1*e1.w);
                if ((l & 15) == 0) atomicAdd(&den[d1*NH + head], x1);
            }
        }
    }
}

// ---------------- k_tail: fused gatfin + MLP, 32 rows per block ----------------
// Per block: gather agg for 32 rows, GEMM (agg @ W_head) with W staged through
// smem (read once per block), LN/ELU/head-mean/+emb into xs, then the 3-layer
// MLP entirely in smem, sigmoid, write out.
__global__ void __launch_bounds__(256) k_tail(
        const int* __restrict__ uidx, const int* __restrict__ sidx,
        const float* __restrict__ uemb, const float* __restrict__ semb,
        const float* __restrict__ uW, const float* __restrict__ sW,
        const float* __restrict__ ubias, const float* __restrict__ ulng, const float* __restrict__ ulnb,
        const float* __restrict__ sbias, const float* __restrict__ slng, const float* __restrict__ slnb,
        const float* __restrict__ W1, const float* __restrict__ b1,
        const float* __restrict__ g1, const float* __restrict__ bb1,
        const float* __restrict__ W2, const float* __restrict__ b2,
        const float* __restrict__ g2, const float* __restrict__ bb2,
        const float* __restrict__ W3, const float* __restrict__ b3,
        float* __restrict__ out) {
    __shared__ float Wch[16*HD];      // 8 KB weight staging chunk
    __shared__ float As[32][HD];      // 16 KB agg (both heads per row)
    __shared__ float xs[32][HD];      // 16 KB MLP activations
    __shared__ int   nodes[2][32];

    int tid = threadIdx.x;
    int w = tid >> 5, l = tid & 31;
    int rbase = blockIdx.x * 32;
    int r0 = w * 4, c0 = l * 4;
    int h = l >> 4;

    if (tid < 32)       nodes[0][tid]      = uidx[rbase + tid];
    else if (tid < 64)  nodes[1][tid - 32] = sidx[rbase + tid - 32];
    __syncthreads();

    // ================= GAT finalize per side =================
    #pragma unroll 1
    for (int side = 0; side < 2; side++) {
        const float* accp = side ? g_acc_s : g_acc_u;
        const float* denp = side ? g_den_s : g_den_u;
        const float* W    = side ? sW : uW;
        const float* bias = side ? sbias : ubias;
        const float* lng  = side ? slng : ulng;
        const float* lnb  = side ? slnb : ulnb;
        const float* emb  = side ? semb : uemb;

        // gather agg = acc/den  (32 rows x 128)
        for (int i = tid; i < 32*HD; i += 256) {
            int rr = i >> 7, cc = i & 127;
            int nd = nodes[side][rr];
            As[rr][cc] = accp[(long long)nd*HD + cc] / denp[nd*NH + (cc >> 6)];
        }

        float acc[4][4] = {};
        for (int kc = 0; kc < 4; kc++) {
            __syncthreads();
            for (int i = tid; i < 16*HD; i += 256) Wch[i] = W[kc*16*HD + i];
            __syncthreads();
            #pragma unroll
            for (int k = 0; k < 16; k++) {
                int ka = h*DIMK + kc*16 + k;
                float a0 = As[r0+0][ka];
                float a1 = As[r0+1][ka];
                float a2 = As[r0+2][ka];
                float a3 = As[r0+3][ka];
                float4 wv = *(const float4*)&Wch[k*HD + c0];
                acc[0][0] += a0*wv.x; acc[0][1] += a0*wv.y; acc[0][2] += a0*wv.z; acc[0][3] += a0*wv.w;
                acc[1][0] += a1*wv.x; acc[1][1] += a1*wv.y; acc[1][2] += a1*wv.z; acc[1][3] += a1*wv.w;
                acc[2][0] += a2*wv.x; acc[2][1] += a2*wv.y; acc[2][2] += a2*wv.z; acc[2][3] += a2*wv.w;
                acc[3][0] += a3*wv.x; acc[3][1] += a3*wv.y; acc[3][2] += a3*wv.z; acc[3][3] += a3*wv.w;
            }
        }

        float4 bv = *(const float4*)&bias[c0];
        float4 gv = *(const float4*)&lng[c0];
        float4 bb = *(const float4*)&lnb[c0];
        #pragma unroll
        for (int i = 0; i < 4; i++) {
            float v0 = acc[i][0] + bv.x, v1 = acc[i][1] + bv.y;
            float v2 = acc[i][2] + bv.z, v3 = acc[i][3] + bv.w;
            float sum = v0+v1+v2+v3;
            #pragma unroll
            for (int o = 16; o; o >>= 1) sum += __shfl_xor_sync(0xffffffffu, sum, o);
            float mean = sum * (1.f/HD);
            float d0 = v0-mean, d1 = v1-mean, d2 = v2-mean, d3 = v3-mean;
            float sq = d0*d0 + d1*d1 + d2*d2 + d3*d3;
            #pragma unroll
            for (int o = 16; o; o >>= 1) sq += __shfl_xor_sync(0xffffffffu, sq, o);
            float rstd = rsqrtf(sq * (1.f/HD) + 1e-5f);
            float n0 = d0*rstd*gv.x + bb.x;
            float n1 = d1*rstd*gv.y + bb.y;
            float n2 = d2*rstd*gv.z + bb.z;
            float n3 = d3*rstd*gv.w + bb.w;
            n0 = n0 > 0.f ? n0 : expm1f(n0);      // ELU
            n1 = n1 > 0.f ? n1 : expm1f(n1);
            n2 = n2 > 0.f ? n2 : expm1f(n2);
            n3 = n3 > 0.f ? n3 : expm1f(n3);
            // head-mean: lane l (<16) pairs with lane l+16 (col c vs c+64)
            float m0 = __shfl_xor_sync(0xffffffffu, n0, 16);
            float m1 = __shfl_xor_sync(0xffffffffu, n1, 16);
            float m2 = __shfl_xor_sync(0xffffffffu, n2, 16);
            float m3 = __shfl_xor_sync(0xffffffffu, n3, 16);
            if (l < 16) {
                int nd = nodes[side][r0+i];
                float4 e4 = *(const float4*)&emb[(long long)nd*DIMK + c0];
                xs[r0+i][side*DIMK + c0 + 0] = 0.5f*(n0+m0) + e4.x;
                xs[r0+i][side*DIMK + c0 + 1] = 0.5f*(n1+m1) + e4.y;
                xs[r0+i][side*DIMK + c0 + 2] = 0.5f*(n2+m2) + e4.z;
                xs[r0+i][side*DIMK + c0 + 3] = 0.5f*(n3+m3) + e4.w;
            }
        }
        __syncthreads();   // As reload / Wch reuse safety for next side
    }

    // ================= MLP: 128->128->128->1 =================
    const float* Wp[2]  = {W1, W2};
    const float* bp[2]  = {b1, b2};
    const float* gp[2]  = {g1, g2};
    const float* bbp[2] = {bb1, bb2};
    float val[4][4];

    #pragma unroll 1
    for (int layer = 0; layer < 2; layer++) {
        float acc[4][4] = {};
        for (int kc = 0; kc < 8; kc++) {
            __syncthreads();
            for (int i = tid; i < 16*HD; i += 256) Wch[i] = Wp[layer][kc*16*HD + i];
            __syncthreads();
            #pragma unroll
            for (int k4 = 0; k4 < 16; k4 += 4) {
                float4 A0 = *(const float4*)&xs[r0+0][kc*16 + k4];
                float4 A1 = *(const float4*)&xs[r0+1][kc*16 + k4];
                float4 A2 = *(const float4*)&xs[r0+2][kc*16 + k4];
                float4 A3 = *(const float4*)&xs[r0+3][kc*16 + k4];
                #pragma unroll
                for (int kk = 0; kk < 4; kk++) {
                    float4 wv = *(const float4*)&Wch[(k4+kk)*HD + c0];
                    float e0 = FCMP(A0,kk), e1 = FCMP(A1,kk), e2 = FCMP(A2,kk), e3 = FCMP(A3,kk);
                    acc[0][0] += e0*wv.x; acc[0][1] += e0*wv.y; acc[0][2] += e0*wv.z; acc[0][3] += e0*wv.w;
                    acc[1][0] += e1*wv.x; acc[1][1] += e1*wv.y; acc[1][2] += e1*wv.z; acc[1][3] += e1*wv.w;
                    acc[2][0] += e2*wv.x; acc[2][1] += e2*wv.y; acc[2][2] += e2*wv.z; acc[2][3] += e2*wv.w;
                    acc[3][0] += e3*wv.x; acc[3][1] += e3*wv.y; acc[3][2] += e3*wv.z; acc[3][3] += e3*wv.w;
                }
            }
        }
        __syncthreads();   // all reads of xs done before overwrite

        float4 bv  = *(const float4*)&bp[layer][c0];
        float4 gv  = *(const float4*)&gp[layer][c0];
        float4 bbv = *(const float4*)&bbp[layer][c0];
        #pragma unroll
        for (int i = 0; i < 4; i++) {
            float a0 = acc[i][0] + bv.x, a1 = acc[i][1] + bv.y;
            float a2 = acc[i][2] + bv.z, a3 = acc[i][3] + bv.w;
            float sum = a0 + a1 + a2 + a3;
            #pragma unroll
            for (int o = 16; o; o >>= 1) sum += __shfl_xor_sync(0xffffffffu, sum, o);
            float mean = sum * (1.f/HD);
            float d0 = a0-mean, d1 = a1-mean, d2 = a2-mean, d3 = a3-mean;
            float sq = d0*d0 + d1*d1 + d2*d2 + d3*d3;
            #pragma unroll
            for (int o = 16; o; o >>= 1) sq += __shfl_xor_sync(0xffffffffu, sq, o);
            float rstd = rsqrtf(sq * (1.f/HD) + 1e-5f);
            float v0 = fmaxf(d0*rstd*gv.x + bbv.x, 0.f);
            float v1 = fmaxf(d1*rstd*gv.y + bbv.y, 0.f);
            float v2 = fmaxf(d2*rstd*gv.z + bbv.z, 0.f);
            float v3 = fmaxf(d3*rstd*gv.w + bbv.w, 0.f);
            xs[r0+i][c0+0] = v0; xs[r0+i][c0+1] = v1;
            xs[r0+i][c0+2] = v2; xs[r0+i][c0+3] = v3;
            val[i][0] = v0; val[i][1] = v1; val[i][2] = v2; val[i][3] = v3;
        }
    }

    float4 w3 = *(const float4*)&W3[c0];
    float bias3 = b3[0];
    #pragma unroll
    for (int i = 0; i < 4; i++) {
        float p = val[i][0]*w3.x + val[i][1]*w3.y + val[i][2]*w3.z + val[i][3]*w3.w;
        #pragma unroll
        for (int o = 16; o; o >>= 1) p += __shfl_xor_sync(0xffffffffu, p, o);
        if (l == 0) out[rbase + r0 + i] = 1.f / (1.f + __expf(-(p + bias3)));
    }
}

// ---------------- launch --------------------------------------------------------
extern "C" void kernel_launch(void* const* d_in, const int* in_sizes, int n_in,
                              void* d_out, int out_size) {
    const int*   uidx  = (const int*)  d_in[0];
    const int*   sidx  = (const int*)  d_in[1];
    const int*   usrc  = (const int*)  d_in[2];
    const int*   udst  = (const int*)  d_in[3];
    const int*   ssrc  = (const int*)  d_in[4];
    const int*   sdst  = (const int*)  d_in[5];
    const float* uemb  = (const float*)d_in[6];
    const float* semb  = (const float*)d_in[7];
    const float* uW    = (const float*)d_in[8];
    const float* ual   = (const float*)d_in[9];
    const float* uar   = (const float*)d_in[10];
    const float* ubias = (const float*)d_in[11];
    const float* ulng  = (const float*)d_in[12];
    const float* ulnb  = (const float*)d_in[13];
    const float* sW    = (const float*)d_in[14];
    const float* sal   = (const float*)d_in[15];
    const float* sar   = (const float*)d_in[16];
    const float* sbias = (const float*)d_in[17];
    const float* slng  = (const float*)d_in[18];
    const float* slnb  = (const float*)d_in[19];
    const float* W1    = (const float*)d_in[20];
    const float* b1    = (const float*)d_in[21];
    const float* g1    = (const float*)d_in[22];
    const float* bb1   = (const float*)d_in[23];
    const float* W2    = (const float*)d_in[24];
    const float* b2    = (const float*)d_in[25];
    const float* g2    = (const float*)d_in[26];
    const float* bb2   = (const float*)d_in[27];
    const float* W3    = (const float*)d_in[28];
    const float* b3    = (const float*)d_in[29];
    float* out = (float*)d_out;

    int B  = in_sizes[0];
    int Eu = in_sizes[2];
    int Es = in_sizes[4];

    k_init<<<33, 256>>>(uW, ual, uar, sW, sal, sar);
    k_mark<<<B, 128>>>(uidx, sidx, uemb, semb);
    {
        int gu = 592, gs = 1184;   // split ~ Eu : Es
        k_edge_all<<<gu + gs, 256>>>(usrc, udst, Eu, ssrc, sdst, Es,
                                     uemb, semb, gu);
    }
    k_tail<<<(B + 31)/32, 256>>>(uidx, sidx, uemb, semb, uW, sW,
                                 ubias, ulng, ulnb, sbias, slng, slnb,
                                 W1, b1, g1, bb1, W2, b2, g2, bb2, W3, b3, out);
}

// round 10
// speedup vs baseline: 3.8529x; 1.2599x over previous
#include <cuda_runtime.h>
#include <math.h>

#define NU 100000
#define NS 200000
#define DIMK 64
#define NH 2
#define HD 128          // NH * DIMK
#define BMAX 16384
#define NUW ((NU+31)/32)
#define NSW ((NS+31)/32)

#define TROWS 64        // rows per k_tail block
#define TTHREADS 512
#define WCH (16*HD)     // weight chunk floats (16 rows x 128)

// ---------------- scratch (static device globals) -------------------------------
__device__ float g_acc_u[NU*HD];     // per-dst: sum ex * emb[src]  (head-major)
__device__ float g_acc_s[NS*HD];
__device__ float g_den_u[NU*NH];
__device__ float g_den_s[NS*NH];
__device__ float g_er_u[NU*NH];      // er for needed dsts, [node*2+h]
__device__ float g_er_s[NS*NH];
__device__ float g_wl_u[DIMK*NH];    // W @ a_l folded vectors, [k*2+h]
__device__ float g_wr_u[DIMK*NH];
__device__ float g_wl_s[DIMK*NH];
__device__ float g_wr_s[DIMK*NH];
__device__ unsigned g_needb_u[NUW];
__device__ unsigned g_needb_s[NSW];

// ---------------- helpers ------------------------------------------------------
__device__ __forceinline__ void red4(float* p, float a, float b, float c, float d) {
    asm volatile("{ .reg .u64 q; cvta.to.global.u64 q, %0;"
                 "  red.global.add.v4.f32 [q], {%1, %2, %3, %4}; }"
                 :: "l"(p), "f"(a), "f"(b), "f"(c), "f"(d) : "memory");
}

#define FCMP(v,kk) ((kk)==0?(v).x:((kk)==1?(v).y:((kk)==2?(v).z:(v).w)))

// ---------------- k_init: reset need bitmasks (blocks 0..N-2) + wvec (last) ----
__global__ void __launch_bounds__(256) k_init(const float* __restrict__ uW,
                                              const float* __restrict__ ual,
                                              const float* __restrict__ uar,
                                              const float* __restrict__ sW,
                                              const float* __restrict__ sal,
                                              const float* __restrict__ sar) {
    if (blockIdx.x == gridDim.x - 1) {
        int tid = threadIdx.x;            // 0..255
        int user = tid < 128;
        int t = tid & 127;
        int k = t >> 1, h = t & 1;
        const float* W  = user ? uW  : sW;
        const float* al = user ? ual : sal;
        const float* ar = user ? uar : sar;
        float accl = 0.f, accr = 0.f;
        #pragma unroll 8
        for (int d = 0; d < DIMK; d++) {
            float w = W[k*HD + h*DIMK + d];
            accl += w * al[h*DIMK + d];
            accr += w * ar[h*DIMK + d];
        }
        if (user) { g_wl_u[k*2+h] = accl; g_wr_u[k*2+h] = accr; }
        else      { g_wl_s[k*2+h] = accl; g_wr_s[k*2+h] = accr; }
        return;
    }
    int i = blockIdx.x*blockDim.x + threadIdx.x;
    int st = (gridDim.x-1)*blockDim.x;
    for (int j = i; j < NUW; j += st) g_needb_u[j] = 0u;
    for (int j = i; j < NSW; j += st) g_needb_s[j] = 0u;
}

// ---------------- k_mark: mark bits, zero acc/den, compute er for dsts ---------
__global__ void __launch_bounds__(128) k_mark(const int* __restrict__ uidx,
                                              const int* __restrict__ sidx,
                                              const float* __restrict__ uemb,
                                              const float* __restrict__ semb) {
    int b = blockIdx.x, t = threadIdx.x;
    int u = uidx[b], s = sidx[b];
    g_acc_u[u*HD + t] = 0.f;
    g_acc_s[s*HD + t] = 0.f;
    if (t < NH) { g_den_u[u*NH + t] = 0.f; g_den_s[s*NH + t] = 0.f; }
    if (t == 0) {
        atomicOr(&g_needb_u[u >> 5], 1u << (u & 31));
        atomicOr(&g_needb_s[s >> 5], 1u << (s & 31));
    }
    // er[d,h] = emb[d] . wr[:,h]; one warp per (side, head)
    {
        int wid = t >> 5, l = t & 31;
        int user = wid < 2, head = wid & 1;
        int node = user ? u : s;
        const float* emb = user ? uemb : semb;
        const float* wr  = user ? g_wr_u : g_wr_s;
        float* er        = user ? g_er_u : g_er_s;
        int k2 = l * 2;
        float2 ev = *(const float2*)&emb[(long long)node*DIMK + k2];
        float p = ev.x * __ldg(&wr[k2*2 + head]) + ev.y * __ldg(&wr[(k2+1)*2 + head]);
        #pragma unroll
        for (int o = 16; o; o >>= 1) p += __shfl_xor_sync(0xffffffffu, p, o);
        if (l == 0) er[node*NH + head] = p;
    }
}

// ---------------- k_edge_all: ballot-compact + 2-edge-ILP drain ----------------
__global__ void __launch_bounds__(256) k_edge_all(const int* __restrict__ usrc,
                                                  const int* __restrict__ udst, int Eu,
                                                  const int* __restrict__ ssrc,
                                                  const int* __restrict__ sdst, int Es,
                                                  const float* __restrict__ uemb,
                                                  const float* __restrict__ semb,
                                                  int splitBlk) {
    int user = (blockIdx.x < splitBlk);
    const int* __restrict__ src = user ? usrc : ssrc;
    const int* __restrict__ dst = user ? udst : sdst;
    int E = user ? Eu : Es;
    const unsigned* __restrict__ needb = user ? g_needb_u : g_needb_s;
    const float* __restrict__ emb = user ? uemb : semb;
    const float* __restrict__ wl  = user ? g_wl_u : g_wl_s;
    const float* __restrict__ er  = user ? g_er_u : g_er_s;
    float* acc = user ? g_acc_u : g_acc_s;
    float* den = user ? g_den_u : g_den_s;
    int vb   = user ? blockIdx.x : blockIdx.x - splitBlk;
    int nblk = user ? splitBlk : gridDim.x - splitBlk;

    int tid = threadIdx.x;
    int wid = tid >> 5, l = tid & 31;
    int head = l >> 4;
    int lq = (l & 15) * 4;

    float wl0 = __ldg(&wl[(lq+0)*2 + head]);
    float wl1 = __ldg(&wl[(lq+1)*2 + head]);
    float wl2 = __ldg(&wl[(lq+2)*2 + head]);
    float wl3 = __ldg(&wl[(lq+3)*2 + head]);

    long long gwarp = (long long)vb*8 + wid;
    long long nwarp = (long long)nblk*8;

    for (long long base = gwarp*32; base < E; base += nwarp*32) {
        long long i = base + l;
        int d = 0, s = 0; bool m = false;
        if (i < E) {
            d = dst[i];
            m = (__ldg(&needb[d >> 5]) >> (d & 31)) & 1u;
        }
        unsigned bal = __ballot_sync(0xffffffffu, m);
        if (m) s = src[i];

        while (bal) {
            int b0 = __ffs(bal) - 1; bal &= bal - 1;
            bool has1 = (bal != 0);
            int b1 = has1 ? (__ffs(bal) - 1) : b0;
            if (has1) bal &= bal - 1;

            int s0 = __shfl_sync(0xffffffffu, s, b0);
            int d0 = __shfl_sync(0xffffffffu, d, b0);
            int s1 = __shfl_sync(0xffffffffu, s, b1);
            int d1 = __shfl_sync(0xffffffffu, d, b1);

            float4 e0 = *(const float4*)&emb[(long long)s0 * DIMK + lq];
            float4 e1 = *(const float4*)&emb[(long long)s1 * DIMK + lq];

            float p0 = e0.x*wl0 + e0.y*wl1 + e0.z*wl2 + e0.w*wl3;
            float p1 = e1.x*wl0 + e1.y*wl1 + e1.z*wl2 + e1.w*wl3;
            #pragma unroll
            for (int o = 8; o; o >>= 1) {
                p0 += __shfl_xor_sync(0xffffffffu, p0, o);
                p1 += __shfl_xor_sync(0xffffffffu, p1, o);
            }
            float a0 = p0 + er[d0*NH + head];
            float a1 = p1 + er[d1*NH + head];
            a0 = a0 > 0.f ? a0 : 0.2f * a0;
            a1 = a1 > 0.f ? a1 : 0.2f * a1;
            float x0 = __expf(a0);
            float x1 = __expf(a1);

            red4(&acc[d0*HD + head*DIMK + lq], x0*e0.x, x0*e0.y, x0*e0.z, x0*e0.w);
            if ((l & 15) == 0) atomicAdd(&den[d0*NH + head], x0);
            if (has1) {
                red4(&acc[d1*HD + head*DIMK + lq], x1*e1.x, x1*e1.y, x1*e1.z, x1*e1.w);
                if ((l & 15) == 0) atomicAdd(&den[d1*NH + head], x1);
            }
        }
    }
}

// ---------------- k_tail v2: 64 rows/block, 512 thr, double-buffered staging ---
__global__ void __launch_bounds__(TTHREADS) k_tail(
        const int* __restrict__ uidx, const int* __restrict__ sidx,
        const float* __restrict__ uemb, const float* __restrict__ semb,
        const float* __restrict__ uW, const float* __restrict__ sW,
        const float* __restrict__ ubias, const float* __restrict__ ulng, const float* __restrict__ ulnb,
        const float* __restrict__ sbias, const float* __restrict__ slng, const float* __restrict__ slnb,
        const float* __restrict__ W1, const float* __restrict__ b1,
        const float* __restrict__ g1, const float* __restrict__ bb1,
        const float* __restrict__ W2, const float* __restrict__ b2,
        const float* __restrict__ g2, const float* __restrict__ bb2,
        const float* __restrict__ W3, const float* __restrict__ b3,
        float* __restrict__ out) {
    extern __shared__ float sm[];
    float* As  = sm;                   // TROWS*HD
    float* xs  = As + TROWS*HD;        // TROWS*HD
    float* Wch = xs + TROWS*HD;        // 2*WCH
    int* nodes = (int*)(Wch + 2*WCH);  // 2*TROWS

    int tid = threadIdx.x;
    int w = tid >> 5, l = tid & 31;    // 16 warps
    int rbase = blockIdx.x * TROWS;
    int r0 = w * 4, c0 = l * 4;
    int h = l >> 4;

    if (tid < TROWS)        nodes[tid]         = uidx[rbase + tid];
    else if (tid < 2*TROWS) nodes[tid]         = sidx[rbase + tid - TROWS];
    __syncthreads();

    // ================= GAT finalize per side =================
    #pragma unroll 1
    for (int side = 0; side < 2; side++) {
        const float* accp = side ? g_acc_s : g_acc_u;
        const float* denp = side ? g_den_s : g_den_u;
        const float* W    = side ? sW : uW;
        const float* bias = side ? sbias : ubias;
        const float* lng  = side ? slng : ulng;
        const float* lnb  = side ? slnb : ulnb;
        const float* emb  = side ? semb : uemb;

        // gather agg = acc/den  (TROWS x 128, float4)
        for (int i = tid; i < TROWS*(HD/4); i += TTHREADS) {
            int rr = i >> 5, cq = i & 31;
            int nd = nodes[side*TROWS + rr];
            float4 a4 = *(const float4*)&accp[(long long)nd*HD + cq*4];
            float inv = 1.f / denp[nd*NH + (cq >> 4)];
            *(float4*)&As[rr*HD + cq*4] = make_float4(a4.x*inv, a4.y*inv, a4.z*inv, a4.w*inv);
        }
        // preload chunk 0
        *(float4*)&Wch[tid*4] = *(const float4*)&W[tid*4];
        __syncthreads();

        float acc[4][4] = {};
        #pragma unroll
        for (int kc = 0; kc < 4; kc++) {
            float4 nxt;
            if (kc < 3) nxt = *(const float4*)&W[(kc+1)*WCH + tid*4];
            const float* Wc = Wch + (kc & 1)*WCH;
            #pragma unroll
            for (int k = 0; k < 16; k++) {
                int ka = h*DIMK + kc*16 + k;
                float a0 = As[(r0+0)*HD + ka];
                float a1 = As[(r0+1)*HD + ka];
                float a2 = As[(r0+2)*HD + ka];
                float a3 = As[(r0+3)*HD + ka];
                float4 wv = *(const float4*)&Wc[k*HD + c0];
                acc[0][0] += a0*wv.x; acc[0][1] += a0*wv.y; acc[0][2] += a0*wv.z; acc[0][3] += a0*wv.w;
                acc[1][0] += a1*wv.x; acc[1][1] += a1*wv.y; acc[1][2] += a1*wv.z; acc[1][3] += a1*wv.w;
                acc[2][0] += a2*wv.x; acc[2][1] += a2*wv.y; acc[2][2] += a2*wv.z; acc[2][3] += a2*wv.w;
                acc[3][0] += a3*wv.x; acc[3][1] += a3*wv.y; acc[3][2] += a3*wv.z; acc[3][3] += a3*wv.w;
            }
            if (kc < 3) *(float4*)&Wch[((kc+1) & 1)*WCH + tid*4] = nxt;
            __syncthreads();
        }

        float4 bv = *(const float4*)&bias[c0];
        float4 gv = *(const float4*)&lng[c0];
        float4 bb = *(const float4*)&lnb[c0];
        #pragma unroll
        for (int i = 0; i < 4; i++) {
            float v0 = acc[i][0] + bv.x, v1 = acc[i][1] + bv.y;
            float v2 = acc[i][2] + bv.z, v3 = acc[i][3] + bv.w;
            float sum = v0+v1+v2+v3;
            #pragma unroll
            for (int o = 16; o; o >>= 1) sum += __shfl_xor_sync(0xffffffffu, sum, o);
            float mean = sum * (1.f/HD);
            float d0 = v0-mean, d1 = v1-mean, d2 = v2-mean, d3 = v3-mean;
            float sq = d0*d0 + d1*d1 + d2*d2 + d3*d3;
            #pragma unroll
            for (int o = 16; o; o >>= 1) sq += __shfl_xor_sync(0xffffffffu, sq, o);
            float rstd = rsqrtf(sq * (1.f/HD) + 1e-5f);
            float n0 = d0*rstd*gv.x + bb.x;
            float n1 = d1*rstd*gv.y + bb.y;
            float n2 = d2*rstd*gv.z + bb.z;
            float n3 = d3*rstd*gv.w + bb.w;
            n0 = n0 > 0.f ? n0 : expm1f(n0);      // ELU
            n1 = n1 > 0.f ? n1 : expm1f(n1);
            n2 = n2 > 0.f ? n2 : expm1f(n2);
            n3 = n3 > 0.f ? n3 : expm1f(n3);
            // head-mean: lane l (<16) pairs with lane l+16 (col c vs c+64)
            float m0 = __shfl_xor_sync(0xffffffffu, n0, 16);
            float m1 = __shfl_xor_sync(0xffffffffu, n1, 16);
            float m2 = __shfl_xor_sync(0xffffffffu, n2, 16);
            float m3 = __shfl_xor_sync(0xffffffffu, n3, 16);
            if (l < 16) {
                int nd = nodes[side*TROWS + r0 + i];
                float4 e4 = *(const float4*)&emb[(long long)nd*DIMK + c0];
                float* xr = &xs[(r0+i)*HD + side*DIMK + c0];
                xr[0] = 0.5f*(n0+m0) + e4.x;
                xr[1] = 0.5f*(n1+m1) + e4.y;
                xr[2] = 0.5f*(n2+m2) + e4.z;
                xr[3] = 0.5f*(n3+m3) + e4.w;
            }
        }
        __syncthreads();   // As/Wch reuse safety for next phase
    }

    // ================= MLP: 128->128->128->1 =================
    const float* Wp[2]  = {W1, W2};
    const float* bp[2]  = {b1, b2};
    const float* gp[2]  = {g1, g2};
    const float* bbp[2] = {bb1, bb2};
    float val[4][4];

    #pragma unroll 1
    for (int layer = 0; layer < 2; layer++) {
        const float* W = Wp[layer];
        // preload chunk 0
        *(float4*)&Wch[tid*4] = *(const float4*)&W[tid*4];
        __syncthreads();

        float acc[4][4] = {};
        #pragma unroll 1
        for (int kc = 0; kc < 8; kc++) {
            float4 nxt;
            if (kc < 7) nxt = *(const float4*)&W[(kc+1)*WCH + tid*4];
            const float* Wc = Wch + (kc & 1)*WCH;
            #pragma unroll
            for (int k4 = 0; k4 < 16; k4 += 4) {
                float4 A0 = *(const float4*)&xs[(r0+0)*HD + kc*16 + k4];
                float4 A1 = *(const float4*)&xs[(r0+1)*HD + kc*16 + k4];
                float4 A2 = *(const float4*)&xs[(r0+2)*HD + kc*16 + k4];
                float4 A3 = *(const float4*)&xs[(r0+3)*HD + kc*16 + k4];
                #pragma unroll
                for (int kk = 0; kk < 4; kk++) {
                    float4 wv = *(const float4*)&Wc[(k4+kk)*HD + c0];
                    float e0 = FCMP(A0,kk), e1 = FCMP(A1,kk), e2 = FCMP(A2,kk), e3 = FCMP(A3,kk);
                    acc[0][0] += e0*wv.x; acc[0][1] += e0*wv.y; acc[0][2] += e0*wv.z; acc[0][3] += e0*wv.w;
                    acc[1][0] += e1*wv.x; acc[1][1] += e1*wv.y; acc[1][2] += e1*wv.z; acc[1][3] += e1*wv.w;
                    acc[2][0] += e2*wv.x; acc[2][1] += e2*wv.y; acc[2][2] += e2*wv.z; acc[2][3] += e2*wv.w;
                    acc[3][0] += e3*wv.x; acc[3][1] += e3*wv.y; acc[3][2] += e3*wv.z; acc[3][3] += e3*wv.w;
                }
            }
            if (kc < 7) *(float4*)&Wch[((kc+1) & 1)*WCH + tid*4] = nxt;
            __syncthreads();
        }

        float4 bv  = *(const float4*)&bp[layer][c0];
        float4 gv  = *(const float4*)&gp[layer][c0];
        float4 bbv = *(const float4*)&bbp[layer][c0];
        #pragma unroll
        for (int i = 0; i < 4; i++) {
            float a0 = acc[i][0] + bv.x, a1 = acc[i][1] + bv.y;
            float a2 = acc[i][2] + bv.z, a3 = acc[i][3] + bv.w;
            float sum = a0 + a1 + a2 + a3;
            #pragma unroll
            for (int o = 16; o; o >>= 1) sum += __shfl_xor_sync(0xffffffffu, sum, o);
            float mean = sum * (1.f/HD);
            float d0 = a0-mean, d1 = a1-mean, d2 = a2-mean, d3 = a3-mean;
            float sq = d0*d0 + d1*d1 + d2*d2 + d3*d3;
            #pragma unroll
            for (int o = 16; o; o >>= 1) sq += __shfl_xor_sync(0xffffffffu, sq, o);
            float rstd = rsqrtf(sq * (1.f/HD) + 1e-5f);
            float v0 = fmaxf(d0*rstd*gv.x + bbv.x, 0.f);
            float v1 = fmaxf(d1*rstd*gv.y + bbv.y, 0.f);
            float v2 = fmaxf(d2*rstd*gv.z + bbv.z, 0.f);
            float v3 = fmaxf(d3*rstd*gv.w + bbv.w, 0.f);
            val[i][0] = v0; val[i][1] = v1; val[i][2] = v2; val[i][3] = v3;
        }
        __syncthreads();   // all reads of xs done (barrier after kc7 above covers compute); ensure before overwrite
        #pragma unroll
        for (int i = 0; i < 4; i++) {
            float* xr = &xs[(r0+i)*HD + c0];
            xr[0] = val[i][0]; xr[1] = val[i][1]; xr[2] = val[i][2]; xr[3] = val[i][3];
        }
        __syncthreads();
    }

    float4 w3 = *(const float4*)&W3[c0];
    float bias3 = b3[0];
    #pragma unroll
    for (int i = 0; i < 4; i++) {
        float p = val[i][0]*w3.x + val[i][1]*w3.y + val[i][2]*w3.z + val[i][3]*w3.w;
        #pragma unroll
        for (int o = 16; o; o >>= 1) p += __shfl_xor_sync(0xffffffffu, p, o);
        if (l == 0) out[rbase + r0 + i] = 1.f / (1.f + __expf(-(p + bias3)));
    }
}

// ---------------- launch --------------------------------------------------------
extern "C" void kernel_launch(void* const* d_in, const int* in_sizes, int n_in,
                              void* d_out, int out_size) {
    const int*   uidx  = (const int*)  d_in[0];
    const int*   sidx  = (const int*)  d_in[1];
    const int*   usrc  = (const int*)  d_in[2];
    const int*   udst  = (const int*)  d_in[3];
    const int*   ssrc  = (const int*)  d_in[4];
    const int*   sdst  = (const int*)  d_in[5];
    const float* uemb  = (const float*)d_in[6];
    const float* semb  = (const float*)d_in[7];
    const float* uW    = (const float*)d_in[8];
    const float* ual   = (const float*)d_in[9];
    const float* uar   = (const float*)d_in[10];
    const float* ubias = (const float*)d_in[11];
    const float* ulng  = (const float*)d_in[12];
    const float* ulnb  = (const float*)d_in[13];
    const float* sW    = (const float*)d_in[14];
    const float* sal   = (const float*)d_in[15];
    const float* sar   = (const float*)d_in[16];
    const float* sbias = (const float*)d_in[17];
    const float* slng  = (const float*)d_in[18];
    const float* slnb  = (const float*)d_in[19];
    const float* W1    = (const float*)d_in[20];
    const float* b1    = (const float*)d_in[21];
    const float* g1    = (const float*)d_in[22];
    const float* bb1   = (const float*)d_in[23];
    const float* W2    = (const float*)d_in[24];
    const float* b2    = (const float*)d_in[25];
    const float* g2    = (const float*)d_in[26];
    const float* bb2   = (const float*)d_in[27];
    const float* W3    = (const float*)d_in[28];
    const float* b3    = (const float*)d_in[29];
    float* out = (float*)d_out;

    int B  = in_sizes[0];
    int Eu = in_sizes[2];
    int Es = in_sizes[4];

    k_init<<<33, 256>>>(uW, ual, uar, sW, sal, sar);
    k_mark<<<B, 128>>>(uidx, sidx, uemb, semb);
    {
        int gu = 592, gs = 1184;   // split ~ Eu : Es
        k_edge_all<<<gu + gs, 256>>>(usrc, udst, Eu, ssrc, sdst, Es,
                                     uemb, semb, gu);
    }
    {
        const int smemBytes = (TROWS*HD + TROWS*HD + 2*WCH) * 4 + 2*TROWS*4;
        cudaFuncSetAttribute(k_tail, cudaFuncAttributeMaxDynamicSharedMemorySize, smemBytes);
        k_tail<<<(B + TROWS - 1)/TROWS, TTHREADS, smemBytes>>>(
            uidx, sidx, uemb, semb, uW, sW,
            ubias, ulng, ulnb, sbias, slng, slnb,
            W1, b1, g1, bb1, W2, b2, g2, bb2, W3, b3, out);
    }
}